// round 4
// baseline (speedup 1.0000x reference)
#include <cuda_runtime.h>
#include <math.h>
#include <stdint.h>

#define NTOK 4096
#define DIM 768
#define QKVN (3*DIM)
#define FFD 3072
#define NE 8
#define NPAIR (NTOK*2)
#define TSEQ 1024
#define NB 4
#define NH 12
#define HD 64

struct Scratch {
  float xln1[(size_t)NTOK*DIM];
  float qkv[(size_t)NTOK*QKVN];
  float attn[(size_t)NTOK*DIM];
  float x1[(size_t)NTOK*DIM];
  float xln2[(size_t)NTOK*DIM];
  float H[(size_t)NPAIR*FFD];
  float slot[(size_t)NPAIR*DIM];
  float pairw[NPAIR];
  int bucket[NE*NPAIR];
  int count[NE];
};
__device__ Scratch g_s;

__device__ __forceinline__ float gelu_f(float v) {
  return 0.5f * v * (1.0f + erff(v * 0.70710678118654752f));
}

__device__ __forceinline__ float to_tf32(float x) {
  unsigned r;
  asm("cvt.rna.tf32.f32 %0, %1;" : "=r"(r) : "f"(x));
  return __uint_as_float(r);
}

__device__ __forceinline__ void mma_tf32(float* c, const float* a, const float* b) {
  asm volatile(
    "mma.sync.aligned.m16n8k8.row.col.f32.tf32.tf32.f32 "
    "{%0,%1,%2,%3},{%4,%5,%6,%7},{%8,%9},{%0,%1,%2,%3};\n"
    : "+f"(c[0]), "+f"(c[1]), "+f"(c[2]), "+f"(c[3])
    : "r"(__float_as_uint(a[0])), "r"(__float_as_uint(a[1])),
      "r"(__float_as_uint(a[2])), "r"(__float_as_uint(a[3])),
      "r"(__float_as_uint(b[0])), "r"(__float_as_uint(b[1])));
}

__device__ __forceinline__ void cp_async16(float* dst, const float* src) {
  uint32_t d = (uint32_t)__cvta_generic_to_shared(dst);
  asm volatile("cp.async.cg.shared.global [%0], [%1], 16;\n" :: "r"(d), "l"(src));
}
__device__ __forceinline__ void cp_commit() {
  asm volatile("cp.async.commit_group;\n");
}
template<int N>
__device__ __forceinline__ void cp_wait() {
  asm volatile("cp.async.wait_group %0;\n" :: "n"(N));
}

// ======================= Multistage tf32 tensor-core GEMM ==========================
// MODE 0: C = A@B                         (QKV)       SPLIT=1 (3xTF32)
// MODE 1: C = A@B + resid                 (proj)      SPLIT=1 (3xTF32)
// MODE 2: gather A rows = pair>>1, gelu   (MoE up)    SPLIT=0
// MODE 3: gather A rows = pair, *pairw    (MoE down)  SPLIT=0
// Block tile 128x128xBK16, 4-stage cp.async pipeline, raw f32 in smem,
// tf32 conversion (and hi/lo split) done at fragment load.
template<int MODE, int SPLIT>
__global__ __launch_bounds__(256, 2)
void mma_gemm(const float* __restrict__ A, const float* __restrict__ Bw,
              float* __restrict__ C, int M, int N, int K,
              const int* __restrict__ bucket, const int* __restrict__ counts,
              const float* __restrict__ resid, const float* __restrict__ pairw)
{
  constexpr int BK  = 16;
  constexpr int STG = 4;
  constexpr int AST = 20;            // A row stride (pad 4): conflict-free frag reads
  constexpr int BST = 136;           // B row stride (pad 8)
  constexpr int ASZ = 128 * AST;     // floats per A stage
  constexpr int BSZ = BK * BST;      // floats per B stage

  extern __shared__ float smx[];
  float* As = smx;                   // [STG][ASZ]
  float* Bs = smx + STG * ASZ;       // [STG][BSZ]
  __shared__ int sPair[128];

  int mcount = M;
  const float* B = Bw;
  if constexpr (MODE >= 2) {
    int e = blockIdx.z;
    mcount = counts[e];
    B += (size_t)e * K * N;
  }
  int m0 = blockIdx.y * 128;
  if (m0 >= mcount) return;
  int n0 = blockIdx.x * 128;
  int tid = threadIdx.x;

  if constexpr (MODE >= 2) {
    if (tid < 128) {
      int gm = m0 + tid;
      int gmc = gm < mcount ? gm : mcount - 1;
      sPair[tid] = bucket[blockIdx.z * NPAIR + gmc];
    }
    __syncthreads();
  }

  // Per-thread gmem source pointers (constant across k-tiles except k offset)
  const float* aSrc[2];
  const float* bSrc[2];
  #pragma unroll
  for (int i = 0; i < 2; i++) {
    int idx = tid + i*256;
    int row = idx >> 2, kc = idx & 3;
    int ar;
    if constexpr (MODE == 2) ar = sPair[row] >> 1;
    else if constexpr (MODE == 3) ar = sPair[row];
    else ar = m0 + row;
    aSrc[i] = A + (size_t)ar * K + kc*4;
    int kr = idx >> 5, nc = idx & 31;
    bSrc[i] = B + (size_t)kr * N + n0 + nc*4;
  }

  auto ldgsts = [&](int stage, int k0) {
    #pragma unroll
    for (int i = 0; i < 2; i++) {
      int idx = tid + i*256;
      int row = idx >> 2, kc = idx & 3;
      cp_async16(As + stage*ASZ + row*AST + kc*4, aSrc[i] + k0);
    }
    #pragma unroll
    for (int i = 0; i < 2; i++) {
      int idx = tid + i*256;
      int kr = idx >> 5, nc = idx & 31;
      cp_async16(Bs + stage*BSZ + kr*BST + nc*4, bSrc[i] + (size_t)k0 * N);
    }
  };

  int lane = tid & 31, wid = tid >> 5;
  int wm = wid >> 1, wn = wid & 1;           // 4(m) x 2(n) warp grid; warp tile 32x64
  int mb = wm*32 + (lane >> 2);
  int nb = wn*64 + (lane >> 2);
  int kq = lane & 3;

  float acc[2][8][4];
  #pragma unroll
  for (int i = 0; i < 2; i++)
    #pragma unroll
    for (int j = 0; j < 8; j++)
      #pragma unroll
      for (int q = 0; q < 4; q++) acc[i][j][q] = 0.f;

  auto compute = [&](int stage) {
    const float* Asb = As + stage*ASZ;
    const float* Bsb = Bs + stage*BSZ;
    #pragma unroll
    for (int s = 0; s < BK/8; s++) {
      int ks = s*8 + kq;
      float ah[2][4], al[2][4];
      #pragma unroll
      for (int mt = 0; mt < 2; mt++) {
        int aw = (mb + mt*16)*AST + ks;
        float r0 = Asb[aw], r1 = Asb[aw + 8*AST], r2 = Asb[aw + 4], r3 = Asb[aw + 8*AST + 4];
        ah[mt][0] = to_tf32(r0); ah[mt][1] = to_tf32(r1);
        ah[mt][2] = to_tf32(r2); ah[mt][3] = to_tf32(r3);
        if constexpr (SPLIT) {
          al[mt][0] = to_tf32(r0 - ah[mt][0]); al[mt][1] = to_tf32(r1 - ah[mt][1]);
          al[mt][2] = to_tf32(r2 - ah[mt][2]); al[mt][3] = to_tf32(r3 - ah[mt][3]);
        }
      }
      #pragma unroll
      for (int nt = 0; nt < 8; nt++) {
        int bw = ks*BST + nb + nt*8;
        float q0 = Bsb[bw], q1 = Bsb[bw + 4*BST];
        float bh[2] = {to_tf32(q0), to_tf32(q1)};
        if constexpr (SPLIT) {
          float bl[2] = {to_tf32(q0 - bh[0]), to_tf32(q1 - bh[1])};
          #pragma unroll
          for (int mt = 0; mt < 2; mt++) {
            mma_tf32(acc[mt][nt], al[mt], bh);
            mma_tf32(acc[mt][nt], ah[mt], bl);
            mma_tf32(acc[mt][nt], ah[mt], bh);
          }
        } else {
          #pragma unroll
          for (int mt = 0; mt < 2; mt++) mma_tf32(acc[mt][nt], ah[mt], bh);
        }
      }
    }
  };

  int nkt = K / BK;
  #pragma unroll
  for (int s = 0; s < STG-1; s++) {
    if (s < nkt) ldgsts(s, s*BK);
    cp_commit();
  }
  for (int kt = 0; kt < nkt; kt++) {
    cp_wait<STG-2>();
    __syncthreads();
    int nxt = kt + STG - 1;
    if (nxt < nkt) ldgsts(nxt % STG, nxt * BK);
    cp_commit();
    compute(kt % STG);
  }

  // epilogue
  #pragma unroll
  for (int mt = 0; mt < 2; mt++) {
    #pragma unroll
    for (int half = 0; half < 2; half++) {
      int rl = wm*32 + mt*16 + (lane >> 2) + half*8;
      int gmi = m0 + rl;
      if (gmi < mcount) {
        int crow; float w = 1.f;
        if constexpr (MODE >= 2) {
          int p = sPair[rl];
          crow = p;
          if constexpr (MODE == 3) w = pairw[p];
        } else crow = gmi;
        #pragma unroll
        for (int nt = 0; nt < 8; nt++) {
          int col = n0 + wn*64 + nt*8 + (lane & 3)*2;
          float v0 = acc[mt][nt][half*2 + 0];
          float v1 = acc[mt][nt][half*2 + 1];
          if constexpr (MODE == 1) {
            const float* rp = resid + (size_t)gmi * N + col;
            v0 += rp[0]; v1 += rp[1];
          }
          if constexpr (MODE == 2) { v0 = gelu_f(v0); v1 = gelu_f(v1); }
          if constexpr (MODE == 3) { v0 *= w; v1 *= w; }
          *(float2*)(C + (size_t)crow * N + col) = make_float2(v0, v1);
        }
      }
    }
  }
}

// ---------------- LayerNorm ----------------
__global__ void ln_kernel(const float* __restrict__ in, const float* __restrict__ gam,
                          const float* __restrict__ bet, float* __restrict__ out) {
  __shared__ float red[256];
  int row = blockIdx.x;
  int tid = threadIdx.x;
  const float* x = in + (size_t)row * DIM;
  float v0 = x[tid], v1 = x[tid+256], v2 = x[tid+512];
  red[tid] = v0+v1+v2; __syncthreads();
  for (int o=128;o;o>>=1){ if (tid<o) red[tid]+=red[tid+o]; __syncthreads(); }
  float mean = red[0] * (1.0f/DIM);
  __syncthreads();
  float d0=v0-mean, d1=v1-mean, d2=v2-mean;
  red[tid] = d0*d0+d1*d1+d2*d2; __syncthreads();
  for (int o=128;o;o>>=1){ if (tid<o) red[tid]+=red[tid+o]; __syncthreads(); }
  float r = rsqrtf(red[0]*(1.0f/DIM) + 1e-5f);
  float* o = out + (size_t)row*DIM;
  o[tid]     = d0*r*gam[tid]     + bet[tid];
  o[tid+256] = d1*r*gam[tid+256] + bet[tid+256];
  o[tid+512] = d2*r*gam[tid+512] + bet[tid+512];
}

// ---------------- Flash attention (fp32) ----------------
__global__ __launch_bounds__(256)
void attn_kernel(const float* __restrict__ qkv, float* __restrict__ out) {
  extern __shared__ float sm[];
  float* Qs = sm;
  float* Ks = sm + 64*68;
  float* Vs = sm + 2*64*68;
  float* Ps = sm + 3*64*68;
  int qt = blockIdx.x, h = blockIdx.y, b = blockIdx.z;
  int tid = threadIdx.x, tx = tid & 15, ty = tid >> 4;
  const float* base = qkv + (size_t)b * TSEQ * QKVN;
  int qcol = h*HD, kcol = DIM + h*HD, vcol = 2*DIM + h*HD;

  for (int idx = tid; idx < 64*64; idx += 256) {
    int r = idx >> 6, d = idx & 63;
    Qs[d*68 + r] = base[(size_t)(qt*64 + r)*QKVN + qcol + d] * 0.125f;
  }
  float m_r[4], l_r[4], O[4][4];
  #pragma unroll
  for (int i=0;i<4;i++){ m_r[i]=-1e30f; l_r[i]=0.f;
    #pragma unroll
    for (int j=0;j<4;j++) O[i][j]=0.f; }

  for (int kt=0; kt<16; kt++) {
    __syncthreads();
    for (int idx = tid; idx < 64*64; idx += 256) {
      int r = idx >> 6, d = idx & 63;
      const float* rp = base + (size_t)(kt*64 + r)*QKVN;
      Ks[d*68 + r] = rp[kcol + d];
      Vs[r*68 + d] = rp[vcol + d];
    }
    __syncthreads();

    float Sf[4][4];
    #pragma unroll
    for (int i=0;i<4;i++)
      #pragma unroll
      for (int j=0;j<4;j++) Sf[i][j]=0.f;
    #pragma unroll 4
    for (int d=0; d<64; d++) {
      float4 a4 = *(const float4*)(Qs + d*68 + ty*4);
      float4 b4 = *(const float4*)(Ks + d*68 + tx*4);
      float aa[4]={a4.x,a4.y,a4.z,a4.w};
      float bb[4]={b4.x,b4.y,b4.z,b4.w};
      #pragma unroll
      for (int i=0;i<4;i++)
        #pragma unroll
        for (int j=0;j<4;j++) Sf[i][j] += aa[i]*bb[j];
    }

    float alpha[4];
    #pragma unroll
    for (int i=0;i<4;i++) {
      float mx = fmaxf(fmaxf(Sf[i][0],Sf[i][1]), fmaxf(Sf[i][2],Sf[i][3]));
      #pragma unroll
      for (int off=1; off<16; off<<=1)
        mx = fmaxf(mx, __shfl_xor_sync(0xffffffffu, mx, off));
      float mnew = fmaxf(m_r[i], mx);
      alpha[i] = expf(m_r[i] - mnew);
      float ps = 0.f;
      #pragma unroll
      for (int j=0;j<4;j++) {
        float p = expf(Sf[i][j] - mnew);
        Ps[(tx*4+j)*68 + (ty*4+i)] = p;
        ps += p;
      }
      #pragma unroll
      for (int off=1; off<16; off<<=1)
        ps += __shfl_xor_sync(0xffffffffu, ps, off);
      l_r[i] = l_r[i]*alpha[i] + ps;
      m_r[i] = mnew;
    }
    #pragma unroll
    for (int i=0;i<4;i++)
      #pragma unroll
      for (int j=0;j<4;j++) O[i][j] *= alpha[i];
    __syncthreads();

    #pragma unroll 4
    for (int kj=0; kj<64; kj++) {
      float4 a4 = *(const float4*)(Ps + kj*68 + ty*4);
      float4 b4 = *(const float4*)(Vs + kj*68 + tx*4);
      float aa[4]={a4.x,a4.y,a4.z,a4.w};
      float bb[4]={b4.x,b4.y,b4.z,b4.w};
      #pragma unroll
      for (int i=0;i<4;i++)
        #pragma unroll
        for (int j=0;j<4;j++) O[i][j] += aa[i]*bb[j];
    }
  }

  #pragma unroll
  for (int i=0;i<4;i++) {
    float inv = 1.0f / l_r[i];
    int q = qt*64 + ty*4 + i;
    float4 v = make_float4(O[i][0]*inv, O[i][1]*inv, O[i][2]*inv, O[i][3]*inv);
    *(float4*)(out + (size_t)(b*TSEQ + q)*DIM + h*HD + tx*4) = v;
  }
}

// ---------------- Router ----------------
__global__ void zero_counts(int* c){ if (threadIdx.x < NE) c[threadIdx.x]=0; }

__global__ void router_kernel(const float* __restrict__ xln2, const float* __restrict__ Wr,
                              int* __restrict__ bucket, float* __restrict__ pairw,
                              int* __restrict__ count) {
  int gw = (int)((blockIdx.x * blockDim.x + threadIdx.x) >> 5);
  int lane = threadIdx.x & 31;
  if (gw >= NTOK) return;
  const float* x = xln2 + (size_t)gw * DIM;
  float lg[NE];
  #pragma unroll
  for (int e=0;e<NE;e++) lg[e]=0.f;
  for (int d=lane; d<DIM; d+=32) {
    float xv = x[d];
    #pragma unroll
    for (int e=0;e<NE;e++) lg[e] += xv * Wr[d*NE + e];
  }
  #pragma unroll
  for (int e=0;e<NE;e++)
    for (int off=16; off; off>>=1) lg[e] += __shfl_xor_sync(0xffffffffu, lg[e], off);
  if (lane == 0) {
    int i0 = 0;
    #pragma unroll
    for (int e=1;e<NE;e++) if (lg[e] > lg[i0]) i0 = e;
    int i1 = (i0==0) ? 1 : 0;
    #pragma unroll
    for (int e=0;e<NE;e++) { if (e==i0) continue; if (lg[e] > lg[i1]) i1 = e; }
    float w0 = 1.f / (1.f + expf(lg[i1] - lg[i0]));
    float w1 = 1.f - w0;
    int p0 = gw*2, p1 = gw*2+1;
    pairw[p0] = w0; pairw[p1] = w1;
    int q0 = atomicAdd(&count[i0], 1); bucket[i0*NPAIR + q0] = p0;
    int q1 = atomicAdd(&count[i1], 1); bucket[i1*NPAIR + q1] = p1;
  }
}

// ---------------- Combine ----------------
__global__ void combine_kernel(const float* __restrict__ x1, const float* __restrict__ slot,
                               float* __restrict__ out) {
  int idx = blockIdx.x * 256 + threadIdx.x;
  if (idx >= NTOK*DIM) return;
  int t = idx / DIM, j = idx - t*DIM;
  out[idx] = x1[idx] + slot[(size_t)(2*t)*DIM + j] + slot[(size_t)(2*t+1)*DIM + j];
}

extern "C" void kernel_launch(void* const* d_in, const int* in_sizes, int n_in,
                              void* d_out, int out_size) {
  const float* x       = (const float*)d_in[0];
  const float* Wqkv    = (const float*)d_in[1];
  const float* Wproj   = (const float*)d_in[2];
  const float* Wrouter = (const float*)d_in[3];
  const float* W1      = (const float*)d_in[4];
  const float* W2      = (const float*)d_in[5];
  const float* ln1g    = (const float*)d_in[6];
  const float* ln1b    = (const float*)d_in[7];
  const float* ln2g    = (const float*)d_in[8];
  const float* ln2b    = (const float*)d_in[9];
  float* out = (float*)d_out;

  Scratch* s = nullptr;
  cudaGetSymbolAddress((void**)&s, g_s);

  const int ATTN_SMEM = 4*64*68*4;
  cudaFuncSetAttribute(attn_kernel, cudaFuncAttributeMaxDynamicSharedMemorySize, ATTN_SMEM);

  // GEMM dynamic smem: 4 stages * (128*20 + 16*136) floats = 75776 bytes
  const int SM_G = (4*(128*20) + 4*(16*136)) * 4;
  cudaFuncSetAttribute(mma_gemm<0,1>, cudaFuncAttributeMaxDynamicSharedMemorySize, SM_G);
  cudaFuncSetAttribute(mma_gemm<1,1>, cudaFuncAttributeMaxDynamicSharedMemorySize, SM_G);
  cudaFuncSetAttribute(mma_gemm<2,0>, cudaFuncAttributeMaxDynamicSharedMemorySize, SM_G);
  cudaFuncSetAttribute(mma_gemm<3,0>, cudaFuncAttributeMaxDynamicSharedMemorySize, SM_G);

  // x -> ln1 -> qkv -> attention -> proj+residual -> x1
  ln_kernel<<<NTOK, 256>>>(x, ln1g, ln1b, s->xln1);
  mma_gemm<0,1><<<dim3(QKVN/128, NTOK/128, 1), 256, SM_G>>>(
      s->xln1, Wqkv, s->qkv, NTOK, QKVN, DIM, nullptr, nullptr, nullptr, nullptr);
  attn_kernel<<<dim3(TSEQ/64, NH, NB), 256, ATTN_SMEM>>>(s->qkv, s->attn);
  mma_gemm<1,1><<<dim3(DIM/128, NTOK/128, 1), 256, SM_G>>>(
      s->attn, Wproj, s->x1, NTOK, DIM, DIM, nullptr, nullptr, x, nullptr);

  // x1 -> ln2 -> router -> MoE -> combine
  ln_kernel<<<NTOK, 256>>>(s->x1, ln2g, ln2b, s->xln2);
  zero_counts<<<1, 32>>>(s->count);
  router_kernel<<<NTOK/8, 256>>>(s->xln2, Wrouter, s->bucket, s->pairw, s->count);
  mma_gemm<2,0><<<dim3(FFD/128, NPAIR/128, NE), 256, SM_G>>>(
      s->xln2, W1, s->H, 0, FFD, DIM, s->bucket, s->count, nullptr, nullptr);
  mma_gemm<3,0><<<dim3(DIM/128, NPAIR/128, NE), 256, SM_G>>>(
      s->H, W2, s->slot, 0, DIM, FFD, s->bucket, s->count, nullptr, s->pairw);
  combine_kernel<<<(NTOK*DIM)/256, 256>>>(s->x1, s->slot, out);
}

// round 6
// speedup vs baseline: 1.5819x; 1.5819x over previous
#include <cuda_runtime.h>
#include <cuda_bf16.h>
#include <math.h>
#include <stdint.h>

#define NTOK 4096
#define DIM 768
#define QKVN (3*DIM)
#define FFD 3072
#define NE 8
#define NPAIR (NTOK*2)
#define TSEQ 1024
#define NB 4
#define NH 12
#define HD 64

// GEMM tiling: 128x128 block, BK=32 (bf16), 8 warps (4m x 2n), warp tile 32x64
#define BKE 32                    // k elements per stage
#define ROWB 80                   // smem row stride bytes (64 data + 16 pad)
#define AREG (128*ROWB)           // 10240 bytes per operand array
#define STGB (4*AREG)             // 40960 bytes per stage (Ah, Al, Bh, Bl)
#define GSMEM (2*STGB)            // double buffer = 81920

struct Scratch {
  float qkv[(size_t)NTOK*QKVN];
  float x1[(size_t)NTOK*DIM];
  float xln2[(size_t)NTOK*DIM];
  float slot[(size_t)NPAIR*DIM];
  __nv_bfloat16 xln1h[(size_t)NTOK*DIM], xln1l[(size_t)NTOK*DIM];
  __nv_bfloat16 attnh[(size_t)NTOK*DIM], attnl[(size_t)NTOK*DIM];
  __nv_bfloat16 xln2h[(size_t)NTOK*DIM], xln2l[(size_t)NTOK*DIM];
  __nv_bfloat16 Hh[(size_t)NPAIR*FFD], Hl[(size_t)NPAIR*FFD];
  __nv_bfloat16 Wqkvth[(size_t)QKVN*DIM], Wqkvtl[(size_t)QKVN*DIM];
  __nv_bfloat16 Wprojth[(size_t)DIM*DIM], Wprojtl[(size_t)DIM*DIM];
  __nv_bfloat16 W1th[(size_t)NE*FFD*DIM], W1tl[(size_t)NE*FFD*DIM];
  __nv_bfloat16 W2th[(size_t)NE*DIM*FFD], W2tl[(size_t)NE*DIM*FFD];
  float pairw[NPAIR];
  int bucket[NE*NPAIR];
  int count[NE];
};
__device__ Scratch g_s;

__device__ __forceinline__ float gelu_f(float v) {
  return 0.5f * v * (1.0f + erff(v * 0.70710678118654752f));
}
__device__ __forceinline__ uint32_t smem_u32(const void* p) {
  uint32_t a;
  asm("{ .reg .u64 t; cvta.to.shared.u64 t, %1; cvt.u32.u64 %0, t; }" : "=r"(a) : "l"(p));
  return a;
}
__device__ __forceinline__ void cp16(uint32_t dst, const void* src) {
  asm volatile("cp.async.cg.shared.global [%0], [%1], 16;\n" :: "r"(dst), "l"(src));
}
__device__ __forceinline__ void cp_commit() { asm volatile("cp.async.commit_group;\n"); }
template<int N> __device__ __forceinline__ void cp_wait() {
  asm volatile("cp.async.wait_group %0;\n" :: "n"(N));
}
__device__ __forceinline__ void ldsm4(uint32_t* r, uint32_t addr) {
  asm volatile("ldmatrix.sync.aligned.m8n8.x4.shared.b16 {%0,%1,%2,%3}, [%4];"
    : "=r"(r[0]), "=r"(r[1]), "=r"(r[2]), "=r"(r[3]) : "r"(addr));
}
__device__ __forceinline__ void mma_bf16(float* c, const uint32_t* a, const uint32_t* b) {
  asm volatile(
    "mma.sync.aligned.m16n8k16.row.col.f32.bf16.bf16.f32 "
    "{%0,%1,%2,%3},{%4,%5,%6,%7},{%8,%9},{%0,%1,%2,%3};\n"
    : "+f"(c[0]), "+f"(c[1]), "+f"(c[2]), "+f"(c[3])
    : "r"(a[0]), "r"(a[1]), "r"(a[2]), "r"(a[3]), "r"(b[0]), "r"(b[1]));
}

// =============== bf16 split-3 GEMM via mma.m16n8k16 + ldmatrix ===============
// MODE 0: qkv = A@B (fp32 out)         MODE 1: x1 = A@B + resid (fp32 out)
// MODE 2: H[pair] = gelu(A[tok]@W1[e]) (bf16 hi/lo out)
// MODE 3: slot[pair] = w*(H[pair]@W2[e]) (fp32 out)
// A: [row][K] bf16 hi/lo.  B: [n][K] bf16 hi/lo (pre-transposed weights).
template<int MODE>
__global__ __launch_bounds__(256, 2)
void gemm_bf3(const __nv_bfloat16* __restrict__ Ahg, const __nv_bfloat16* __restrict__ Alg,
              const __nv_bfloat16* __restrict__ Bhg, const __nv_bfloat16* __restrict__ Blg,
              float* __restrict__ Cf, __nv_bfloat16* __restrict__ Chi, __nv_bfloat16* __restrict__ Clo,
              int M, int N, int K,
              const int* __restrict__ bucket, const int* __restrict__ counts,
              const float* __restrict__ resid, const float* __restrict__ pairw)
{
  extern __shared__ char dynsm[];
  __shared__ int sPair[128];

  int tid = threadIdx.x, wid = tid >> 5, lane = tid & 31;
  int e = (MODE >= 2) ? blockIdx.z : 0;
  int mcount = (MODE >= 2) ? counts[e] : M;
  int m0 = blockIdx.y * 128;
  if (m0 >= mcount) return;
  int n0 = blockIdx.x * 128;

  if constexpr (MODE >= 2) {
    Bhg += (size_t)e * K * N;
    Blg += (size_t)e * K * N;
    if (tid < 128) {
      int gm = m0 + tid;
      sPair[tid] = bucket[e * NPAIR + (gm < mcount ? gm : mcount - 1)];
    }
    __syncthreads();
  }

  uint32_t sbase = smem_u32(dynsm);

  // A row ids for this thread's two cp.async rows
  int arow[2];
  #pragma unroll
  for (int i = 0; i < 2; i++) {
    int row = (tid + i*256) >> 2;
    if constexpr (MODE == 2)      arow[i] = sPair[row] >> 1;
    else if constexpr (MODE == 3) arow[i] = sPair[row];
    else                          arow[i] = m0 + row;
  }

  auto load_chunk = [&](int stage, int k0) {
    uint32_t st = sbase + stage * STGB;
    #pragma unroll
    for (int i = 0; i < 2; i++) {
      int u = tid + i*256;
      int row = u >> 2, c = u & 3;
      uint32_t so = row*ROWB + c*16;
      size_t go = (size_t)arow[i] * K + k0 + c*8;
      cp16(st + so,        Ahg + go);
      cp16(st + AREG + so, Alg + go);
    }
    #pragma unroll
    for (int i = 0; i < 2; i++) {
      int u = tid + i*256;
      int row = u >> 2, c = u & 3;
      uint32_t so = row*ROWB + c*16;
      size_t go = (size_t)(n0 + row) * K + k0 + c*8;
      cp16(st + 2*AREG + so, Bhg + go);
      cp16(st + 3*AREG + so, Blg + go);
    }
    cp_commit();
  };

  int wm = wid >> 1, wn = wid & 1;
  uint32_t aoff = (uint32_t)((wm*32 + (lane & 15))*ROWB + (lane >> 4)*16);
  uint32_t boff = (uint32_t)((wn*64 + (lane & 7) + ((lane >> 4) << 3))*ROWB +
                             ((lane >> 3) & 1)*16);

  float acc[2][8][4];
  #pragma unroll
  for (int i = 0; i < 2; i++)
    #pragma unroll
    for (int j = 0; j < 8; j++)
      #pragma unroll
      for (int q = 0; q < 4; q++) acc[i][j][q] = 0.f;

  auto compute = [&](int stage) {
    uint32_t st = sbase + stage * STGB;
    #pragma unroll
    for (int ks = 0; ks < 2; ks++) {
      uint32_t kb = ks * 32;   // 16 bf16 = 32 bytes
      uint32_t ah[2][4], al[2][4];
      ldsm4(ah[0], st + aoff + kb);
      ldsm4(ah[1], st + aoff + 16*ROWB + kb);
      ldsm4(al[0], st + AREG + aoff + kb);
      ldsm4(al[1], st + AREG + aoff + 16*ROWB + kb);
      #pragma unroll
      for (int g = 0; g < 4; g++) {
        uint32_t bh[4], bl[4];
        ldsm4(bh, st + 2*AREG + boff + g*16*ROWB + kb);
        ldsm4(bl, st + 3*AREG + boff + g*16*ROWB + kb);
        #pragma unroll
        for (int t = 0; t < 2; t++) {
          #pragma unroll
          for (int mt = 0; mt < 2; mt++) {
            float* c = acc[mt][g*2 + t];
            mma_bf16(c, ah[mt], bl + t*2);
            mma_bf16(c, al[mt], bh + t*2);
            mma_bf16(c, ah[mt], bh + t*2);
          }
        }
      }
    }
  };

  int nkt = K / BKE;
  load_chunk(0, 0);
  for (int kt = 0; kt < nkt; kt++) {
    int p = kt & 1;
    cp_wait<0>();
    __syncthreads();
    if (kt + 1 < nkt) load_chunk(p ^ 1, (kt + 1) * BKE);
    compute(p);
    __syncthreads();
  }

  // epilogue (C fragment: rows lane>>2 & +8, cols 2*(lane&3) within n8 tile)
  #pragma unroll
  for (int mt = 0; mt < 2; mt++) {
    #pragma unroll
    for (int half = 0; half < 2; half++) {
      int rl = wm*32 + mt*16 + (lane >> 2) + half*8;
      int gmi = m0 + rl;
      if (gmi < mcount) {
        int crow; float w = 1.f;
        if constexpr (MODE >= 2) {
          int pr = sPair[rl];
          crow = pr;
          if constexpr (MODE == 3) w = pairw[pr];
        } else crow = gmi;
        #pragma unroll
        for (int nt = 0; nt < 8; nt++) {
          int col = n0 + wn*64 + nt*8 + (lane & 3)*2;
          float v0 = acc[mt][nt][half*2 + 0];
          float v1 = acc[mt][nt][half*2 + 1];
          if constexpr (MODE == 0) {
            *(float2*)(Cf + (size_t)crow * N + col) = make_float2(v0, v1);
          } else if constexpr (MODE == 1) {
            const float* rp = resid + (size_t)gmi * N + col;
            *(float2*)(Cf + (size_t)crow * N + col) = make_float2(v0 + rp[0], v1 + rp[1]);
          } else if constexpr (MODE == 2) {
            v0 = gelu_f(v0); v1 = gelu_f(v1);
            __nv_bfloat16 h0 = __float2bfloat16(v0);
            __nv_bfloat16 h1 = __float2bfloat16(v1);
            __nv_bfloat162 hv; hv.x = h0; hv.y = h1;
            __nv_bfloat162 lv;
            lv.x = __float2bfloat16(v0 - __bfloat162float(h0));
            lv.y = __float2bfloat16(v1 - __bfloat162float(h1));
            *(__nv_bfloat162*)(Chi + (size_t)crow * N + col) = hv;
            *(__nv_bfloat162*)(Clo + (size_t)crow * N + col) = lv;
          } else {
            *(float2*)(Cf + (size_t)crow * N + col) = make_float2(v0 * w, v1 * w);
          }
        }
      }
    }
  }
}

// --------- transpose + bf16 split: in [E][R][C] f32 -> out [E][C][R] hi/lo ---------
__global__ void transpose_split(const float* __restrict__ in, __nv_bfloat16* __restrict__ oh,
                                __nv_bfloat16* __restrict__ ol, int R, int C) {
  __shared__ float t[32][33];
  size_t eo = (size_t)blockIdx.z * R * C;
  int c0 = blockIdx.x * 32, r0 = blockIdx.y * 32;
  int tx = threadIdx.x, ty = threadIdx.y;
  #pragma unroll
  for (int i = 0; i < 32; i += 8)
    t[ty + i][tx] = in[eo + (size_t)(r0 + ty + i) * C + c0 + tx];
  __syncthreads();
  #pragma unroll
  for (int i = 0; i < 32; i += 8) {
    float v = t[tx][ty + i];
    size_t o = eo + (size_t)(c0 + ty + i) * R + r0 + tx;
    __nv_bfloat16 h = __float2bfloat16(v);
    oh[o] = h;
    ol[o] = __float2bfloat16(v - __bfloat162float(h));
  }
}

// ---------------- LayerNorm (writes optional f32 + bf16 hi/lo) ----------------
__global__ void ln_kernel(const float* __restrict__ in, const float* __restrict__ gam,
                          const float* __restrict__ bet, float* __restrict__ of,
                          __nv_bfloat16* __restrict__ oh, __nv_bfloat16* __restrict__ ol) {
  __shared__ float red[256];
  int row = blockIdx.x, tid = threadIdx.x;
  const float* x = in + (size_t)row * DIM;
  float v0 = x[tid], v1 = x[tid+256], v2 = x[tid+512];
  red[tid] = v0+v1+v2; __syncthreads();
  for (int o=128;o;o>>=1){ if (tid<o) red[tid]+=red[tid+o]; __syncthreads(); }
  float mean = red[0] * (1.0f/DIM);
  __syncthreads();
  float d0=v0-mean, d1=v1-mean, d2=v2-mean;
  red[tid] = d0*d0+d1*d1+d2*d2; __syncthreads();
  for (int o=128;o;o>>=1){ if (tid<o) red[tid]+=red[tid+o]; __syncthreads(); }
  float r = rsqrtf(red[0]*(1.0f/DIM) + 1e-5f);
  size_t base = (size_t)row * DIM;
  #pragma unroll
  for (int j = 0; j < 3; j++) {
    int c = tid + j*256;
    float d = (j==0) ? d0 : (j==1) ? d1 : d2;
    float v = d*r*gam[c] + bet[c];
    if (of) of[base + c] = v;
    __nv_bfloat16 h = __float2bfloat16(v);
    oh[base + c] = h;
    ol[base + c] = __float2bfloat16(v - __bfloat162float(h));
  }
}

// ---------------- Flash attention (fp32 compute, bf16 hi/lo output) ----------------
__global__ __launch_bounds__(256)
void attn_kernel(const float* __restrict__ qkv, __nv_bfloat16* __restrict__ oh,
                 __nv_bfloat16* __restrict__ ol) {
  extern __shared__ float sm[];
  float* Qs = sm;
  float* Ks = sm + 64*68;
  float* Vs = sm + 2*64*68;
  float* Ps = sm + 3*64*68;
  int qt = blockIdx.x, h = blockIdx.y, b = blockIdx.z;
  int tid = threadIdx.x, tx = tid & 15, ty = tid >> 4;
  const float* base = qkv + (size_t)b * TSEQ * QKVN;
  int qcol = h*HD, kcol = DIM + h*HD, vcol = 2*DIM + h*HD;

  for (int idx = tid; idx < 64*64; idx += 256) {
    int r = idx >> 6, d = idx & 63;
    Qs[d*68 + r] = base[(size_t)(qt*64 + r)*QKVN + qcol + d] * 0.125f;
  }
  float m_r[4], l_r[4], O[4][4];
  #pragma unroll
  for (int i=0;i<4;i++){ m_r[i]=-1e30f; l_r[i]=0.f;
    #pragma unroll
    for (int j=0;j<4;j++) O[i][j]=0.f; }

  for (int kt=0; kt<16; kt++) {
    __syncthreads();
    for (int idx = tid; idx < 64*64; idx += 256) {
      int r = idx >> 6, d = idx & 63;
      const float* rp = base + (size_t)(kt*64 + r)*QKVN;
      Ks[d*68 + r] = rp[kcol + d];
      Vs[r*68 + d] = rp[vcol + d];
    }
    __syncthreads();

    float Sf[4][4];
    #pragma unroll
    for (int i=0;i<4;i++)
      #pragma unroll
      for (int j=0;j<4;j++) Sf[i][j]=0.f;
    #pragma unroll 4
    for (int d=0; d<64; d++) {
      float4 a4 = *(const float4*)(Qs + d*68 + ty*4);
      float4 b4 = *(const float4*)(Ks + d*68 + tx*4);
      float aa[4]={a4.x,a4.y,a4.z,a4.w};
      float bb[4]={b4.x,b4.y,b4.z,b4.w};
      #pragma unroll
      for (int i=0;i<4;i++)
        #pragma unroll
        for (int j=0;j<4;j++) Sf[i][j] += aa[i]*bb[j];
    }

    float alpha[4];
    #pragma unroll
    for (int i=0;i<4;i++) {
      float mx = fmaxf(fmaxf(Sf[i][0],Sf[i][1]), fmaxf(Sf[i][2],Sf[i][3]));
      #pragma unroll
      for (int off=1; off<16; off<<=1)
        mx = fmaxf(mx, __shfl_xor_sync(0xffffffffu, mx, off));
      float mnew = fmaxf(m_r[i], mx);
      alpha[i] = expf(m_r[i] - mnew);
      float ps = 0.f;
      #pragma unroll
      for (int j=0;j<4;j++) {
        float p = expf(Sf[i][j] - mnew);
        Ps[(tx*4+j)*68 + (ty*4+i)] = p;
        ps += p;
      }
      #pragma unroll
      for (int off=1; off<16; off<<=1)
        ps += __shfl_xor_sync(0xffffffffu, ps, off);
      l_r[i] = l_r[i]*alpha[i] + ps;
      m_r[i] = mnew;
    }
    #pragma unroll
    for (int i=0;i<4;i++)
      #pragma unroll
      for (int j=0;j<4;j++) O[i][j] *= alpha[i];
    __syncthreads();

    #pragma unroll 4
    for (int kj=0; kj<64; kj++) {
      float4 a4 = *(const float4*)(Ps + kj*68 + ty*4);
      float4 b4 = *(const float4*)(Vs + kj*68 + tx*4);
      float aa[4]={a4.x,a4.y,a4.z,a4.w};
      float bb[4]={b4.x,b4.y,b4.z,b4.w};
      #pragma unroll
      for (int i=0;i<4;i++)
        #pragma unroll
        for (int j=0;j<4;j++) O[i][j] += aa[i]*bb[j];
    }
  }

  #pragma unroll
  for (int i=0;i<4;i++) {
    float inv = 1.0f / l_r[i];
    int q = qt*64 + ty*4 + i;
    size_t o = (size_t)(b*TSEQ + q)*DIM + h*HD + tx*4;
    #pragma unroll
    for (int j=0;j<4;j++) {
      float v = O[i][j]*inv;
      __nv_bfloat16 hh = __float2bfloat16(v);
      oh[o+j] = hh;
      ol[o+j] = __float2bfloat16(v - __bfloat162float(hh));
    }
  }
}

// ---------------- Router ----------------
__global__ void zero_counts(int* c){ if (threadIdx.x < NE) c[threadIdx.x]=0; }

__global__ void router_kernel(const float* __restrict__ xln2, const float* __restrict__ Wr,
                              int* __restrict__ bucket, float* __restrict__ pairw,
                              int* __restrict__ count) {
  int gw = (int)((blockIdx.x * blockDim.x + threadIdx.x) >> 5);
  int lane = threadIdx.x & 31;
  if (gw >= NTOK) return;
  const float* x = xln2 + (size_t)gw * DIM;
  float lg[NE];
  #pragma unroll
  for (int e=0;e<NE;e++) lg[e]=0.f;
  for (int d=lane; d<DIM; d+=32) {
    float xv = x[d];
    #pragma unroll
    for (int e=0;e<NE;e++) lg[e] += xv * Wr[d*NE + e];
  }
  #pragma unroll
  for (int e=0;e<NE;e++)
    for (int off=16; off; off>>=1) lg[e] += __shfl_xor_sync(0xffffffffu, lg[e], off);
  if (lane == 0) {
    int i0 = 0;
    #pragma unroll
    for (int e=1;e<NE;e++) if (lg[e] > lg[i0]) i0 = e;
    int i1 = (i0==0) ? 1 : 0;
    #pragma unroll
    for (int e=0;e<NE;e++) { if (e==i0) continue; if (lg[e] > lg[i1]) i1 = e; }
    float w0 = 1.f / (1.f + expf(lg[i1] - lg[i0]));
    float w1 = 1.f - w0;
    int p0 = gw*2, p1 = gw*2+1;
    pairw[p0] = w0; pairw[p1] = w1;
    int q0 = atomicAdd(&count[i0], 1); bucket[i0*NPAIR + q0] = p0;
    int q1 = atomicAdd(&count[i1], 1); bucket[i1*NPAIR + q1] = p1;
  }
}

// ---------------- Combine ----------------
__global__ void combine_kernel(const float* __restrict__ x1, const float* __restrict__ slot,
                               float* __restrict__ out) {
  int idx = blockIdx.x * 256 + threadIdx.x;
  if (idx >= NTOK*DIM) return;
  int t = idx / DIM, j = idx - t*DIM;
  out[idx] = x1[idx] + slot[(size_t)(2*t)*DIM + j] + slot[(size_t)(2*t+1)*DIM + j];
}

extern "C" void kernel_launch(void* const* d_in, const int* in_sizes, int n_in,
                              void* d_out, int out_size) {
  const float* x       = (const float*)d_in[0];
  const float* Wqkv    = (const float*)d_in[1];
  const float* Wproj   = (const float*)d_in[2];
  const float* Wrouter = (const float*)d_in[3];
  const float* W1      = (const float*)d_in[4];
  const float* W2      = (const float*)d_in[5];
  const float* ln1g    = (const float*)d_in[6];
  const float* ln1b    = (const float*)d_in[7];
  const float* ln2g    = (const float*)d_in[8];
  const float* ln2b    = (const float*)d_in[9];
  float* out = (float*)d_out;

  Scratch* s = nullptr;
  cudaGetSymbolAddress((void**)&s, g_s);

  const int ATTN_SMEM = 4*64*68*4;
  cudaFuncSetAttribute(attn_kernel, cudaFuncAttributeMaxDynamicSharedMemorySize, ATTN_SMEM);
  cudaFuncSetAttribute(gemm_bf3<0>, cudaFuncAttributeMaxDynamicSharedMemorySize, GSMEM);
  cudaFuncSetAttribute(gemm_bf3<1>, cudaFuncAttributeMaxDynamicSharedMemorySize, GSMEM);
  cudaFuncSetAttribute(gemm_bf3<2>, cudaFuncAttributeMaxDynamicSharedMemorySize, GSMEM);
  cudaFuncSetAttribute(gemm_bf3<3>, cudaFuncAttributeMaxDynamicSharedMemorySize, GSMEM);

  dim3 tb(32, 8);
  transpose_split<<<dim3(QKVN/32, DIM/32, 1), tb>>>(Wqkv, s->Wqkvth, s->Wqkvtl, DIM, QKVN);
  transpose_split<<<dim3(DIM/32, DIM/32, 1), tb>>>(Wproj, s->Wprojth, s->Wprojtl, DIM, DIM);
  transpose_split<<<dim3(FFD/32, DIM/32, NE), tb>>>(W1, s->W1th, s->W1tl, DIM, FFD);
  transpose_split<<<dim3(DIM/32, FFD/32, NE), tb>>>(W2, s->W2th, s->W2tl, FFD, DIM);

  // x -> ln1 -> qkv -> attention -> proj+residual -> x1
  ln_kernel<<<NTOK, 256>>>(x, ln1g, ln1b, nullptr, s->xln1h, s->xln1l);
  gemm_bf3<0><<<dim3(QKVN/128, NTOK/128, 1), 256, GSMEM>>>(
      s->xln1h, s->xln1l, s->Wqkvth, s->Wqkvtl, s->qkv, nullptr, nullptr,
      NTOK, QKVN, DIM, nullptr, nullptr, nullptr, nullptr);
  attn_kernel<<<dim3(TSEQ/64, NH, NB), 256, ATTN_SMEM>>>(s->qkv, s->attnh, s->attnl);
  gemm_bf3<1><<<dim3(DIM/128, NTOK/128, 1), 256, GSMEM>>>(
      s->attnh, s->attnl, s->Wprojth, s->Wprojtl, s->x1, nullptr, nullptr,
      NTOK, DIM, DIM, nullptr, nullptr, x, nullptr);

  // x1 -> ln2 -> router -> MoE -> combine
  ln_kernel<<<NTOK, 256>>>(s->x1, ln2g, ln2b, s->xln2, s->xln2h, s->xln2l);
  zero_counts<<<1, 32>>>(s->count);
  router_kernel<<<NTOK/8, 256>>>(s->xln2, Wrouter, s->bucket, s->pairw, s->count);
  gemm_bf3<2><<<dim3(FFD/128, NPAIR/128, NE), 256, GSMEM>>>(
      s->xln2h, s->xln2l, s->W1th, s->W1tl, nullptr, s->Hh, s->Hl,
      0, FFD, DIM, s->bucket, s->count, nullptr, nullptr);
  gemm_bf3<3><<<dim3(DIM/128, NPAIR/128, NE), 256, GSMEM>>>(
      s->Hh, s->Hl, s->W2th, s->W2tl, s->slot, nullptr, nullptr,
      0, DIM, FFD, s->bucket, s->count, nullptr, s->pairw);
  combine_kernel<<<(NTOK*DIM)/256, 256>>>(s->x1, s->slot, out);
}

// round 7
// speedup vs baseline: 2.1329x; 1.3483x over previous
#include <cuda_runtime.h>
#include <cuda_fp16.h>
#include <math.h>
#include <stdint.h>

#define NTOK 4096
#define DIM 768
#define QKVN (3*DIM)
#define FFD 3072
#define NE 8
#define NPAIR (NTOK*2)
#define TSEQ 1024
#define NB 4
#define NH 12
#define HD 64

// GEMM tiling: 128x128 block, BK=32 (fp16), 8 warps (4m x 2n), warp tile 32x64
#define BKE 32
#define ROWB 80                    // 64 data bytes + 16 pad
#define AREG (128*ROWB)            // 10240 B per operand region
#define GSMEM_S (2*4*AREG)         // split kernel: 2 stages x (Ah,Al,Bh,Bl) = 81920
#define GSMEM_1 (2*2*AREG)         // single kernel: 2 stages x (Ah,Bh) = 40960

struct Scratch {
  float qkv[(size_t)NTOK*QKVN];
  float x1[(size_t)NTOK*DIM];
  float xln2[(size_t)NTOK*DIM];
  float slot[(size_t)NPAIR*DIM];
  __half xln1h[(size_t)NTOK*DIM], xln1l[(size_t)NTOK*DIM];
  __half attnh[(size_t)NTOK*DIM], attnl[(size_t)NTOK*DIM];
  __half xln2h[(size_t)NTOK*DIM];
  __half Hh[(size_t)NPAIR*FFD];
  __half Wqkvth[(size_t)QKVN*DIM], Wqkvtl[(size_t)QKVN*DIM];
  __half Wprojth[(size_t)DIM*DIM], Wprojtl[(size_t)DIM*DIM];
  __half W1th[(size_t)NE*FFD*DIM];
  __half W2th[(size_t)NE*DIM*FFD];
  float pairw[NPAIR];
  int bucket[NE*NPAIR];
  int count[NE];
};
__device__ Scratch g_s;

__device__ __forceinline__ float gelu_f(float v) {
  return 0.5f * v * (1.0f + erff(v * 0.70710678118654752f));
}
__device__ __forceinline__ uint32_t smem_u32(const void* p) {
  uint32_t a;
  asm("{ .reg .u64 t; cvta.to.shared.u64 t, %1; cvt.u32.u64 %0, t; }" : "=r"(a) : "l"(p));
  return a;
}
__device__ __forceinline__ void cp16(uint32_t dst, const void* src) {
  asm volatile("cp.async.cg.shared.global [%0], [%1], 16;\n" :: "r"(dst), "l"(src));
}
__device__ __forceinline__ void cp_commit() { asm volatile("cp.async.commit_group;\n"); }
template<int N> __device__ __forceinline__ void cp_wait() {
  asm volatile("cp.async.wait_group %0;\n" :: "n"(N));
}
__device__ __forceinline__ void ldsm4(uint32_t* r, uint32_t addr) {
  asm volatile("ldmatrix.sync.aligned.m8n8.x4.shared.b16 {%0,%1,%2,%3}, [%4];"
    : "=r"(r[0]), "=r"(r[1]), "=r"(r[2]), "=r"(r[3]) : "r"(addr));
}
__device__ __forceinline__ void mma_f16(float* c, const uint32_t* a, const uint32_t* b) {
  asm volatile(
    "mma.sync.aligned.m16n8k16.row.col.f32.f16.f16.f32 "
    "{%0,%1,%2,%3},{%4,%5,%6,%7},{%8,%9},{%0,%1,%2,%3};\n"
    : "+f"(c[0]), "+f"(c[1]), "+f"(c[2]), "+f"(c[3])
    : "r"(a[0]), "r"(a[1]), "r"(a[2]), "r"(a[3]), "r"(b[0]), "r"(b[1]));
}

// =============== fp16 GEMM via mma.m16n8k16 + ldmatrix ===============
// SPLIT=1 (3-term compensated, ~1e-7):  MODE 0 qkv, MODE 1 proj+resid
// SPLIT=0 (single fp16, ~2e-4):         MODE 2 MoE-up gelu->fp16, MODE 3 MoE-down *w
template<int MODE, int SPLIT>
__global__ __launch_bounds__(256, 2)
void gemm_f16(const __half* __restrict__ Ahg, const __half* __restrict__ Alg,
              const __half* __restrict__ Bhg, const __half* __restrict__ Blg,
              float* __restrict__ Cf, __half* __restrict__ Chalf,
              int M, int N, int K,
              const int* __restrict__ bucket, const int* __restrict__ counts,
              const float* __restrict__ resid, const float* __restrict__ pairw)
{
  constexpr int NOPS = SPLIT ? 4 : 2;
  constexpr int STGB = NOPS * AREG;
  extern __shared__ char dynsm[];
  __shared__ int sPair[128];

  int tid = threadIdx.x, wid = tid >> 5, lane = tid & 31;
  int e = (MODE >= 2) ? blockIdx.z : 0;
  int mcount = (MODE >= 2) ? counts[e] : M;
  int m0 = blockIdx.y * 128;
  if (m0 >= mcount) return;
  int n0 = blockIdx.x * 128;

  if constexpr (MODE >= 2) {
    Bhg += (size_t)e * K * N;
    if (tid < 128) {
      int gm = m0 + tid;
      sPair[tid] = bucket[e * NPAIR + (gm < mcount ? gm : mcount - 1)];
    }
    __syncthreads();
  }

  uint32_t sbase = smem_u32(dynsm);

  int arow[2];
  #pragma unroll
  for (int i = 0; i < 2; i++) {
    int row = (tid + i*256) >> 2;
    if constexpr (MODE == 2)      arow[i] = sPair[row] >> 1;
    else if constexpr (MODE == 3) arow[i] = sPair[row];
    else                          arow[i] = m0 + row;
  }

  auto load_chunk = [&](int stage, int k0) {
    uint32_t st = sbase + stage * STGB;
    #pragma unroll
    for (int i = 0; i < 2; i++) {
      int u = tid + i*256;
      int row = u >> 2, c = u & 3;
      uint32_t so = row*ROWB + c*16;
      size_t go = (size_t)arow[i] * K + k0 + c*8;
      cp16(st + so, Ahg + go);
      if constexpr (SPLIT) cp16(st + AREG + so, Alg + go);
    }
    #pragma unroll
    for (int i = 0; i < 2; i++) {
      int u = tid + i*256;
      int row = u >> 2, c = u & 3;
      uint32_t so = row*ROWB + c*16;
      size_t go = (size_t)(n0 + row) * K + k0 + c*8;
      cp16(st + (SPLIT ? 2 : 1)*AREG + so, Bhg + go);
      if constexpr (SPLIT) cp16(st + 3*AREG + so, Blg + go);
    }
    cp_commit();
  };

  int wm = wid >> 1, wn = wid & 1;
  uint32_t aoff = (uint32_t)((wm*32 + (lane & 15))*ROWB + (lane >> 4)*16);
  uint32_t boff = (uint32_t)((wn*64 + (lane & 7) + ((lane >> 4) << 3))*ROWB +
                             ((lane >> 3) & 1)*16);

  float acc[2][8][4];
  #pragma unroll
  for (int i = 0; i < 2; i++)
    #pragma unroll
    for (int j = 0; j < 8; j++)
      #pragma unroll
      for (int q = 0; q < 4; q++) acc[i][j][q] = 0.f;

  auto compute = [&](int stage) {
    uint32_t st = sbase + stage * STGB;
    uint32_t bbase = st + (SPLIT ? 2 : 1)*AREG;
    #pragma unroll
    for (int ks = 0; ks < 2; ks++) {
      uint32_t kb = ks * 32;
      uint32_t ah[2][4], al[2][4];
      ldsm4(ah[0], st + aoff + kb);
      ldsm4(ah[1], st + aoff + 16*ROWB + kb);
      if constexpr (SPLIT) {
        ldsm4(al[0], st + AREG + aoff + kb);
        ldsm4(al[1], st + AREG + aoff + 16*ROWB + kb);
      }
      #pragma unroll
      for (int g = 0; g < 4; g++) {
        uint32_t bh[4], bl[4];
        ldsm4(bh, bbase + boff + g*16*ROWB + kb);
        if constexpr (SPLIT) ldsm4(bl, st + 3*AREG + boff + g*16*ROWB + kb);
        #pragma unroll
        for (int t = 0; t < 2; t++) {
          #pragma unroll
          for (int mt = 0; mt < 2; mt++) {
            float* c = acc[mt][g*2 + t];
            if constexpr (SPLIT) {
              mma_f16(c, ah[mt], bl + t*2);
              mma_f16(c, al[mt], bh + t*2);
            }
            mma_f16(c, ah[mt], bh + t*2);
          }
        }
      }
    }
  };

  int nkt = K / BKE;
  load_chunk(0, 0);
  for (int kt = 0; kt < nkt; kt++) {
    int p = kt & 1;
    cp_wait<0>();
    __syncthreads();
    if (kt + 1 < nkt) load_chunk(p ^ 1, (kt + 1) * BKE);
    compute(p);
    __syncthreads();
  }

  #pragma unroll
  for (int mt = 0; mt < 2; mt++) {
    #pragma unroll
    for (int half = 0; half < 2; half++) {
      int rl = wm*32 + mt*16 + (lane >> 2) + half*8;
      int gmi = m0 + rl;
      if (gmi < mcount) {
        int crow; float w = 1.f;
        if constexpr (MODE >= 2) {
          int pr = sPair[rl];
          crow = pr;
          if constexpr (MODE == 3) w = pairw[pr];
        } else crow = gmi;
        #pragma unroll
        for (int nt = 0; nt < 8; nt++) {
          int col = n0 + wn*64 + nt*8 + (lane & 3)*2;
          float v0 = acc[mt][nt][half*2 + 0];
          float v1 = acc[mt][nt][half*2 + 1];
          if constexpr (MODE == 0) {
            *(float2*)(Cf + (size_t)crow * N + col) = make_float2(v0, v1);
          } else if constexpr (MODE == 1) {
            const float* rp = resid + (size_t)gmi * N + col;
            *(float2*)(Cf + (size_t)crow * N + col) = make_float2(v0 + rp[0], v1 + rp[1]);
          } else if constexpr (MODE == 2) {
            __half2 hv;
            hv.x = __float2half_rn(gelu_f(v0));
            hv.y = __float2half_rn(gelu_f(v1));
            *(__half2*)(Chalf + (size_t)crow * N + col) = hv;
          } else {
            *(float2*)(Cf + (size_t)crow * N + col) = make_float2(v0 * w, v1 * w);
          }
        }
      }
    }
  }
}

// --------- transpose + fp16 split: in [E][R][C] f32 -> out [E][C][R] hi (+lo) ---------
template<int WITH_LO>
__global__ void transpose_split(const float* __restrict__ in, __half* __restrict__ oh,
                                __half* __restrict__ ol, int R, int C) {
  __shared__ float t[32][33];
  size_t eo = (size_t)blockIdx.z * R * C;
  int c0 = blockIdx.x * 32, r0 = blockIdx.y * 32;
  int tx = threadIdx.x, ty = threadIdx.y;
  #pragma unroll
  for (int i = 0; i < 32; i += 8)
    t[ty + i][tx] = in[eo + (size_t)(r0 + ty + i) * C + c0 + tx];
  __syncthreads();
  #pragma unroll
  for (int i = 0; i < 32; i += 8) {
    float v = t[tx][ty + i];
    size_t o = eo + (size_t)(c0 + ty + i) * R + r0 + tx;
    __half h = __float2half_rn(v);
    oh[o] = h;
    if constexpr (WITH_LO) ol[o] = __float2half_rn(v - __half2float(h));
  }
}

// ---------------- LayerNorm (f32 opt + fp16 hi (+lo)) ----------------
__global__ void ln_kernel(const float* __restrict__ in, const float* __restrict__ gam,
                          const float* __restrict__ bet, float* __restrict__ of,
                          __half* __restrict__ oh, __half* __restrict__ ol) {
  __shared__ float red[256];
  int row = blockIdx.x, tid = threadIdx.x;
  const float* x = in + (size_t)row * DIM;
  float v0 = x[tid], v1 = x[tid+256], v2 = x[tid+512];
  red[tid] = v0+v1+v2; __syncthreads();
  for (int o=128;o;o>>=1){ if (tid<o) red[tid]+=red[tid+o]; __syncthreads(); }
  float mean = red[0] * (1.0f/DIM);
  __syncthreads();
  float d0=v0-mean, d1=v1-mean, d2=v2-mean;
  red[tid] = d0*d0+d1*d1+d2*d2; __syncthreads();
  for (int o=128;o;o>>=1){ if (tid<o) red[tid]+=red[tid+o]; __syncthreads(); }
  float r = rsqrtf(red[0]*(1.0f/DIM) + 1e-5f);
  size_t base = (size_t)row * DIM;
  #pragma unroll
  for (int j = 0; j < 3; j++) {
    int c = tid + j*256;
    float d = (j==0) ? d0 : (j==1) ? d1 : d2;
    float v = d*r*gam[c] + bet[c];
    if (of) of[base + c] = v;
    __half h = __float2half_rn(v);
    oh[base + c] = h;
    if (ol) ol[base + c] = __float2half_rn(v - __half2float(h));
  }
}

// ---------------- Flash attention (fp32, fast exp, fp16 hi/lo out) ----------------
__global__ __launch_bounds__(256)
void attn_kernel(const float* __restrict__ qkv, __half* __restrict__ oh,
                 __half* __restrict__ ol) {
  extern __shared__ float sm[];
  float* Qs = sm;
  float* Ks = sm + 64*68;
  float* Vs = sm + 2*64*68;
  float* Ps = sm + 3*64*68;
  int qt = blockIdx.x, h = blockIdx.y, b = blockIdx.z;
  int tid = threadIdx.x, tx = tid & 15, ty = tid >> 4;
  const float* base = qkv + (size_t)b * TSEQ * QKVN;
  int qcol = h*HD, kcol = DIM + h*HD, vcol = 2*DIM + h*HD;

  for (int idx = tid; idx < 64*64; idx += 256) {
    int r = idx >> 6, d = idx & 63;
    Qs[d*68 + r] = base[(size_t)(qt*64 + r)*QKVN + qcol + d] * 0.125f;
  }
  float m_r[4], l_r[4], O[4][4];
  #pragma unroll
  for (int i=0;i<4;i++){ m_r[i]=-1e30f; l_r[i]=0.f;
    #pragma unroll
    for (int j=0;j<4;j++) O[i][j]=0.f; }

  for (int kt=0; kt<16; kt++) {
    __syncthreads();
    for (int idx = tid; idx < 64*64; idx += 256) {
      int r = idx >> 6, d = idx & 63;
      const float* rp = base + (size_t)(kt*64 + r)*QKVN;
      Ks[d*68 + r] = rp[kcol + d];
      Vs[r*68 + d] = rp[vcol + d];
    }
    __syncthreads();

    float Sf[4][4];
    #pragma unroll
    for (int i=0;i<4;i++)
      #pragma unroll
      for (int j=0;j<4;j++) Sf[i][j]=0.f;
    #pragma unroll 4
    for (int d=0; d<64; d++) {
      float4 a4 = *(const float4*)(Qs + d*68 + ty*4);
      float4 b4 = *(const float4*)(Ks + d*68 + tx*4);
      float aa[4]={a4.x,a4.y,a4.z,a4.w};
      float bb[4]={b4.x,b4.y,b4.z,b4.w};
      #pragma unroll
      for (int i=0;i<4;i++)
        #pragma unroll
        for (int j=0;j<4;j++) Sf[i][j] += aa[i]*bb[j];
    }

    float alpha[4];
    #pragma unroll
    for (int i=0;i<4;i++) {
      float mx = fmaxf(fmaxf(Sf[i][0],Sf[i][1]), fmaxf(Sf[i][2],Sf[i][3]));
      #pragma unroll
      for (int off=1; off<16; off<<=1)
        mx = fmaxf(mx, __shfl_xor_sync(0xffffffffu, mx, off));
      float mnew = fmaxf(m_r[i], mx);
      alpha[i] = __expf(m_r[i] - mnew);
      float ps = 0.f;
      #pragma unroll
      for (int j=0;j<4;j++) {
        float p = __expf(Sf[i][j] - mnew);
        Ps[(tx*4+j)*68 + (ty*4+i)] = p;
        ps += p;
      }
      #pragma unroll
      for (int off=1; off<16; off<<=1)
        ps += __shfl_xor_sync(0xffffffffu, ps, off);
      l_r[i] = l_r[i]*alpha[i] + ps;
      m_r[i] = mnew;
    }
    #pragma unroll
    for (int i=0;i<4;i++)
      #pragma unroll
      for (int j=0;j<4;j++) O[i][j] *= alpha[i];
    __syncthreads();

    #pragma unroll 4
    for (int kj=0; kj<64; kj++) {
      float4 a4 = *(const float4*)(Ps + kj*68 + ty*4);
      float4 b4 = *(const float4*)(Vs + kj*68 + tx*4);
      float aa[4]={a4.x,a4.y,a4.z,a4.w};
      float bb[4]={b4.x,b4.y,b4.z,b4.w};
      #pragma unroll
      for (int i=0;i<4;i++)
        #pragma unroll
        for (int j=0;j<4;j++) O[i][j] += aa[i]*bb[j];
    }
  }

  #pragma unroll
  for (int i=0;i<4;i++) {
    float inv = 1.0f / l_r[i];
    int q = qt*64 + ty*4 + i;
    size_t o = (size_t)(b*TSEQ + q)*DIM + h*HD + tx*4;
    #pragma unroll
    for (int j=0;j<4;j++) {
      float v = O[i][j]*inv;
      __half hh = __float2half_rn(v);
      oh[o+j] = hh;
      ol[o+j] = __float2half_rn(v - __half2float(hh));
    }
  }
}

// ---------------- Router ----------------
__global__ void zero_counts(int* c){ if (threadIdx.x < NE) c[threadIdx.x]=0; }

__global__ void router_kernel(const float* __restrict__ xln2, const float* __restrict__ Wr,
                              int* __restrict__ bucket, float* __restrict__ pairw,
                              int* __restrict__ count) {
  int gw = (int)((blockIdx.x * blockDim.x + threadIdx.x) >> 5);
  int lane = threadIdx.x & 31;
  if (gw >= NTOK) return;
  const float* x = xln2 + (size_t)gw * DIM;
  float lg[NE];
  #pragma unroll
  for (int e=0;e<NE;e++) lg[e]=0.f;
  for (int d=lane; d<DIM; d+=32) {
    float xv = x[d];
    #pragma unroll
    for (int e=0;e<NE;e++) lg[e] += xv * Wr[d*NE + e];
  }
  #pragma unroll
  for (int e=0;e<NE;e++)
    for (int off=16; off; off>>=1) lg[e] += __shfl_xor_sync(0xffffffffu, lg[e], off);
  if (lane == 0) {
    int i0 = 0;
    #pragma unroll
    for (int e=1;e<NE;e++) if (lg[e] > lg[i0]) i0 = e;
    int i1 = (i0==0) ? 1 : 0;
    #pragma unroll
    for (int e=0;e<NE;e++) { if (e==i0) continue; if (lg[e] > lg[i1]) i1 = e; }
    float w0 = 1.f / (1.f + expf(lg[i1] - lg[i0]));
    float w1 = 1.f - w0;
    int p0 = gw*2, p1 = gw*2+1;
    pairw[p0] = w0; pairw[p1] = w1;
    int q0 = atomicAdd(&count[i0], 1); bucket[i0*NPAIR + q0] = p0;
    int q1 = atomicAdd(&count[i1], 1); bucket[i1*NPAIR + q1] = p1;
  }
}

// ---------------- Combine ----------------
__global__ void combine_kernel(const float* __restrict__ x1, const float* __restrict__ slot,
                               float* __restrict__ out) {
  int idx = blockIdx.x * 256 + threadIdx.x;
  if (idx >= NTOK*DIM) return;
  int t = idx / DIM, j = idx - t*DIM;
  out[idx] = x1[idx] + slot[(size_t)(2*t)*DIM + j] + slot[(size_t)(2*t+1)*DIM + j];
}

extern "C" void kernel_launch(void* const* d_in, const int* in_sizes, int n_in,
                              void* d_out, int out_size) {
  const float* x       = (const float*)d_in[0];
  const float* Wqkv    = (const float*)d_in[1];
  const float* Wproj   = (const float*)d_in[2];
  const float* Wrouter = (const float*)d_in[3];
  const float* W1      = (const float*)d_in[4];
  const float* W2      = (const float*)d_in[5];
  const float* ln1g    = (const float*)d_in[6];
  const float* ln1b    = (const float*)d_in[7];
  const float* ln2g    = (const float*)d_in[8];
  const float* ln2b    = (const float*)d_in[9];
  float* out = (float*)d_out;

  Scratch* s = nullptr;
  cudaGetSymbolAddress((void**)&s, g_s);

  const int ATTN_SMEM = 4*64*68*4;
  cudaFuncSetAttribute(attn_kernel, cudaFuncAttributeMaxDynamicSharedMemorySize, ATTN_SMEM);
  cudaFuncSetAttribute(gemm_f16<0,1>, cudaFuncAttributeMaxDynamicSharedMemorySize, GSMEM_S);
  cudaFuncSetAttribute(gemm_f16<1,1>, cudaFuncAttributeMaxDynamicSharedMemorySize, GSMEM_S);
  cudaFuncSetAttribute(gemm_f16<2,0>, cudaFuncAttributeMaxDynamicSharedMemorySize, GSMEM_1);
  cudaFuncSetAttribute(gemm_f16<3,0>, cudaFuncAttributeMaxDynamicSharedMemorySize, GSMEM_1);

  dim3 tb(32, 8);
  transpose_split<1><<<dim3(QKVN/32, DIM/32, 1), tb>>>(Wqkv, s->Wqkvth, s->Wqkvtl, DIM, QKVN);
  transpose_split<1><<<dim3(DIM/32, DIM/32, 1), tb>>>(Wproj, s->Wprojth, s->Wprojtl, DIM, DIM);
  transpose_split<0><<<dim3(FFD/32, DIM/32, NE), tb>>>(W1, s->W1th, nullptr, DIM, FFD);
  transpose_split<0><<<dim3(DIM/32, FFD/32, NE), tb>>>(W2, s->W2th, nullptr, FFD, DIM);

  // x -> ln1 -> qkv -> attention -> proj+residual -> x1
  ln_kernel<<<NTOK, 256>>>(x, ln1g, ln1b, nullptr, s->xln1h, s->xln1l);
  gemm_f16<0,1><<<dim3(QKVN/128, NTOK/128, 1), 256, GSMEM_S>>>(
      s->xln1h, s->xln1l, s->Wqkvth, s->Wqkvtl, s->qkv, nullptr,
      NTOK, QKVN, DIM, nullptr, nullptr, nullptr, nullptr);
  attn_kernel<<<dim3(TSEQ/64, NH, NB), 256, ATTN_SMEM>>>(s->qkv, s->attnh, s->attnl);
  gemm_f16<1,1><<<dim3(DIM/128, NTOK/128, 1), 256, GSMEM_S>>>(
      s->attnh, s->attnl, s->Wprojth, s->Wprojtl, s->x1, nullptr,
      NTOK, DIM, DIM, nullptr, nullptr, x, nullptr);

  // x1 -> ln2 -> router -> MoE -> combine
  ln_kernel<<<NTOK, 256>>>(s->x1, ln2g, ln2b, s->xln2, s->xln2h, nullptr);
  zero_counts<<<1, 32>>>(s->count);
  router_kernel<<<NTOK/8, 256>>>(s->xln2, Wrouter, s->bucket, s->pairw, s->count);
  gemm_f16<2,0><<<dim3(FFD/128, NPAIR/128, NE), 256, GSMEM_1>>>(
      s->xln2h, nullptr, s->W1th, nullptr, nullptr, s->Hh,
      0, FFD, DIM, s->bucket, s->count, nullptr, nullptr);
  gemm_f16<3,0><<<dim3(DIM/128, NPAIR/128, NE), 256, GSMEM_1>>>(
      s->Hh, nullptr, s->W2th, nullptr, s->slot, nullptr,
      0, DIM, FFD, s->bucket, s->count, nullptr, s->pairw);
  combine_kernel<<<(NTOK*DIM)/256, 256>>>(s->x1, s->slot, out);
}

// round 8
// speedup vs baseline: 3.1035x; 1.4551x over previous
#include <cuda_runtime.h>
#include <cuda_fp16.h>
#include <math.h>
#include <stdint.h>

#define NTOK 4096
#define DIM 768
#define QKVN (3*DIM)
#define FFD 3072
#define NE 8
#define NPAIR (NTOK*2)
#define TSEQ 1024
#define NB 4
#define NH 12
#define HD 64

// GEMM tiling: 128x128 block, BK=32 (fp16), 8 warps (4m x 2n)
#define BKE 32
#define ROWB 80
#define AREG (128*ROWB)
#define GSMEM_S (2*4*AREG)
#define GSMEM_1 (2*2*AREG)

// attention smem row stride: 64 halves = 128B + 16 pad
#define AT_ROWB 144
#define AT_Q   0
#define AT_QL  (128*AT_ROWB)
#define AT_KH  (2*128*AT_ROWB)
#define AT_KL  (AT_KH + 64*AT_ROWB)
#define AT_VH  (AT_KH + 2*64*AT_ROWB)
#define AT_VL  (AT_KH + 3*64*AT_ROWB)
#define AT_SMEM (AT_KH + 4*64*AT_ROWB)   // 73728

struct Scratch {
  float x1[(size_t)NTOK*DIM];
  float xln2[(size_t)NTOK*DIM];
  float slot[(size_t)NPAIR*DIM];
  __half qkvh[(size_t)NTOK*QKVN], qkvl[(size_t)NTOK*QKVN];
  __half xln1h[(size_t)NTOK*DIM], xln1l[(size_t)NTOK*DIM];
  __half attnh[(size_t)NTOK*DIM], attnl[(size_t)NTOK*DIM];
  __half xln2h[(size_t)NTOK*DIM];
  __half Hh[(size_t)NPAIR*FFD];
  __half Wqkvth[(size_t)QKVN*DIM], Wqkvtl[(size_t)QKVN*DIM];
  __half Wprojth[(size_t)DIM*DIM], Wprojtl[(size_t)DIM*DIM];
  __half W1th[(size_t)NE*FFD*DIM];
  __half W2th[(size_t)NE*DIM*FFD];
  float pairw[NPAIR];
  int bucket[NE*NPAIR];
  int count[NE];
};
__device__ Scratch g_s;

__device__ __forceinline__ float gelu_f(float v) {
  return 0.5f * v * (1.0f + erff(v * 0.70710678118654752f));
}
__device__ __forceinline__ uint32_t smem_u32(const void* p) {
  uint32_t a;
  asm("{ .reg .u64 t; cvta.to.shared.u64 t, %1; cvt.u32.u64 %0, t; }" : "=r"(a) : "l"(p));
  return a;
}
__device__ __forceinline__ void cp16(uint32_t dst, const void* src) {
  asm volatile("cp.async.cg.shared.global [%0], [%1], 16;\n" :: "r"(dst), "l"(src));
}
__device__ __forceinline__ void cp_commit() { asm volatile("cp.async.commit_group;\n"); }
template<int N> __device__ __forceinline__ void cp_wait() {
  asm volatile("cp.async.wait_group %0;\n" :: "n"(N));
}
__device__ __forceinline__ void ldsm4(uint32_t* r, uint32_t addr) {
  asm volatile("ldmatrix.sync.aligned.m8n8.x4.shared.b16 {%0,%1,%2,%3}, [%4];"
    : "=r"(r[0]), "=r"(r[1]), "=r"(r[2]), "=r"(r[3]) : "r"(addr));
}
__device__ __forceinline__ void ldsm4t(uint32_t* r, uint32_t addr) {
  asm volatile("ldmatrix.sync.aligned.m8n8.x4.trans.shared.b16 {%0,%1,%2,%3}, [%4];"
    : "=r"(r[0]), "=r"(r[1]), "=r"(r[2]), "=r"(r[3]) : "r"(addr));
}
__device__ __forceinline__ void mma_f16(float* c, const uint32_t* a, const uint32_t* b) {
  asm volatile(
    "mma.sync.aligned.m16n8k16.row.col.f32.f16.f16.f32 "
    "{%0,%1,%2,%3},{%4,%5,%6,%7},{%8,%9},{%0,%1,%2,%3};\n"
    : "+f"(c[0]), "+f"(c[1]), "+f"(c[2]), "+f"(c[3])
    : "r"(a[0]), "r"(a[1]), "r"(a[2]), "r"(a[3]), "r"(b[0]), "r"(b[1]));
}
__device__ __forceinline__ uint32_t packh2(float x, float y) {
  __half2 h; h.x = __float2half_rn(x); h.y = __float2half_rn(y);
  return *(uint32_t*)&h;
}

// =============== fp16 GEMM via mma.m16n8k16 + ldmatrix ===============
// SPLIT=1: MODE 0 qkv->fp16 hi/lo (Q scaled), MODE 1 proj+resid->f32
// SPLIT=0: MODE 2 MoE-up gelu->fp16, MODE 3 MoE-down *w ->f32
template<int MODE, int SPLIT>
__global__ __launch_bounds__(256, 2)
void gemm_f16(const __half* __restrict__ Ahg, const __half* __restrict__ Alg,
              const __half* __restrict__ Bhg, const __half* __restrict__ Blg,
              float* __restrict__ Cf, __half* __restrict__ Chalf, __half* __restrict__ Chalf2,
              int M, int N, int K,
              const int* __restrict__ bucket, const int* __restrict__ counts,
              const float* __restrict__ resid, const float* __restrict__ pairw)
{
  constexpr int NOPS = SPLIT ? 4 : 2;
  constexpr int STGB = NOPS * AREG;
  extern __shared__ char dynsm[];
  __shared__ int sPair[128];

  int tid = threadIdx.x, wid = tid >> 5, lane = tid & 31;
  int e = (MODE >= 2) ? blockIdx.z : 0;
  int mcount = (MODE >= 2) ? counts[e] : M;
  int m0 = blockIdx.y * 128;
  if (m0 >= mcount) return;
  int n0 = blockIdx.x * 128;

  if constexpr (MODE >= 2) {
    Bhg += (size_t)e * K * N;
    if (tid < 128) {
      int gm = m0 + tid;
      sPair[tid] = bucket[e * NPAIR + (gm < mcount ? gm : mcount - 1)];
    }
    __syncthreads();
  }

  uint32_t sbase = smem_u32(dynsm);

  int arow[2];
  #pragma unroll
  for (int i = 0; i < 2; i++) {
    int row = (tid + i*256) >> 2;
    if constexpr (MODE == 2)      arow[i] = sPair[row] >> 1;
    else if constexpr (MODE == 3) arow[i] = sPair[row];
    else                          arow[i] = m0 + row;
  }

  auto load_chunk = [&](int stage, int k0) {
    uint32_t st = sbase + stage * STGB;
    #pragma unroll
    for (int i = 0; i < 2; i++) {
      int u = tid + i*256;
      int row = u >> 2, c = u & 3;
      uint32_t so = row*ROWB + c*16;
      size_t go = (size_t)arow[i] * K + k0 + c*8;
      cp16(st + so, Ahg + go);
      if constexpr (SPLIT) cp16(st + AREG + so, Alg + go);
    }
    #pragma unroll
    for (int i = 0; i < 2; i++) {
      int u = tid + i*256;
      int row = u >> 2, c = u & 3;
      uint32_t so = row*ROWB + c*16;
      size_t go = (size_t)(n0 + row) * K + k0 + c*8;
      cp16(st + (SPLIT ? 2 : 1)*AREG + so, Bhg + go);
      if constexpr (SPLIT) cp16(st + 3*AREG + so, Blg + go);
    }
    cp_commit();
  };

  int wm = wid >> 1, wn = wid & 1;
  uint32_t aoff = (uint32_t)((wm*32 + (lane & 15))*ROWB + (lane >> 4)*16);
  uint32_t boff = (uint32_t)((wn*64 + (lane & 7) + ((lane >> 4) << 3))*ROWB +
                             ((lane >> 3) & 1)*16);

  float acc[2][8][4];
  #pragma unroll
  for (int i = 0; i < 2; i++)
    #pragma unroll
    for (int j = 0; j < 8; j++)
      #pragma unroll
      for (int q = 0; q < 4; q++) acc[i][j][q] = 0.f;

  auto compute = [&](int stage) {
    uint32_t st = sbase + stage * STGB;
    uint32_t bbase = st + (SPLIT ? 2 : 1)*AREG;
    #pragma unroll
    for (int ks = 0; ks < 2; ks++) {
      uint32_t kb = ks * 32;
      uint32_t ah[2][4], al[2][4];
      ldsm4(ah[0], st + aoff + kb);
      ldsm4(ah[1], st + aoff + 16*ROWB + kb);
      if constexpr (SPLIT) {
        ldsm4(al[0], st + AREG + aoff + kb);
        ldsm4(al[1], st + AREG + aoff + 16*ROWB + kb);
      }
      #pragma unroll
      for (int g = 0; g < 4; g++) {
        uint32_t bh[4], bl[4];
        ldsm4(bh, bbase + boff + g*16*ROWB + kb);
        if constexpr (SPLIT) ldsm4(bl, st + 3*AREG + boff + g*16*ROWB + kb);
        #pragma unroll
        for (int t = 0; t < 2; t++) {
          #pragma unroll
          for (int mt = 0; mt < 2; mt++) {
            float* c = acc[mt][g*2 + t];
            if constexpr (SPLIT) {
              mma_f16(c, ah[mt], bl + t*2);
              mma_f16(c, al[mt], bh + t*2);
            }
            mma_f16(c, ah[mt], bh + t*2);
          }
        }
      }
    }
  };

  int nkt = K / BKE;
  load_chunk(0, 0);
  for (int kt = 0; kt < nkt; kt++) {
    int p = kt & 1;
    cp_wait<0>();
    __syncthreads();
    if (kt + 1 < nkt) load_chunk(p ^ 1, (kt + 1) * BKE);
    compute(p);
    __syncthreads();
  }

  #pragma unroll
  for (int mt = 0; mt < 2; mt++) {
    #pragma unroll
    for (int half = 0; half < 2; half++) {
      int rl = wm*32 + mt*16 + (lane >> 2) + half*8;
      int gmi = m0 + rl;
      if (gmi < mcount) {
        int crow; float w = 1.f;
        if constexpr (MODE >= 2) {
          int pr = sPair[rl];
          crow = pr;
          if constexpr (MODE == 3) w = pairw[pr];
        } else crow = gmi;
        #pragma unroll
        for (int nt = 0; nt < 8; nt++) {
          int col = n0 + wn*64 + nt*8 + (lane & 3)*2;
          float v0 = acc[mt][nt][half*2 + 0];
          float v1 = acc[mt][nt][half*2 + 1];
          if constexpr (MODE == 0) {
            float sc = (col < DIM) ? 0.125f : 1.0f;
            v0 *= sc; v1 *= sc;
            __half h0 = __float2half_rn(v0), h1 = __float2half_rn(v1);
            __half2 hv; hv.x = h0; hv.y = h1;
            __half2 lv;
            lv.x = __float2half_rn(v0 - __half2float(h0));
            lv.y = __float2half_rn(v1 - __half2float(h1));
            *(__half2*)(Chalf + (size_t)crow * N + col) = hv;
            *(__half2*)(Chalf2 + (size_t)crow * N + col) = lv;
          } else if constexpr (MODE == 1) {
            const float* rp = resid + (size_t)gmi * N + col;
            *(float2*)(Cf + (size_t)crow * N + col) = make_float2(v0 + rp[0], v1 + rp[1]);
          } else if constexpr (MODE == 2) {
            __half2 hv;
            hv.x = __float2half_rn(gelu_f(v0));
            hv.y = __float2half_rn(gelu_f(v1));
            *(__half2*)(Chalf + (size_t)crow * N + col) = hv;
          } else {
            *(float2*)(Cf + (size_t)crow * N + col) = make_float2(v0 * w, v1 * w);
          }
        }
      }
    }
  }
}

// ============ Tensor-core flash attention (fp16 split-3, fp32 softmax) ============
// grid (TSEQ/128, NH, NB), 256 threads, 8 warps x 16 query rows.
__global__ __launch_bounds__(256, 2)
void attn_tc(const __half* __restrict__ qkvh, const __half* __restrict__ qkvl,
             __half* __restrict__ oh, __half* __restrict__ ol) {
  extern __shared__ char dynsm[];
  uint32_t sb = smem_u32(dynsm);
  int tid = threadIdx.x, wid = tid >> 5, lane = tid & 31;
  int qt = blockIdx.x, h = blockIdx.y, b = blockIdx.z;
  int qcol = h*HD, kcol = DIM + h*HD, vcol = 2*DIM + h*HD;
  size_t rowbase = (size_t)b * TSEQ;

  // load Q tile (128 x 64) hi/lo
  #pragma unroll
  for (int i = 0; i < 4; i++) {
    int u = tid + i*256;
    int r = u >> 3, c = u & 7;
    size_t go = (rowbase + qt*128 + r) * QKVN + qcol + c*8;
    uint32_t so = r*AT_ROWB + c*16;
    cp16(sb + AT_Q  + so, qkvh + go);
    cp16(sb + AT_QL + so, qkvl + go);
  }
  cp_commit();

  uint32_t aoff = (uint32_t)((wid*16 + (lane & 15))*AT_ROWB + (lane >> 4)*16);
  uint32_t kboff = (uint32_t)(((lane & 7) + ((lane >> 4) << 3))*AT_ROWB + ((lane >> 3) & 1)*16);
  uint32_t voff = (uint32_t)((lane & 15)*AT_ROWB + (lane >> 4)*16);

  float O[8][4];
  #pragma unroll
  for (int i = 0; i < 8; i++)
    #pragma unroll
    for (int j = 0; j < 4; j++) O[i][j] = 0.f;
  float m0 = -1e30f, m1 = -1e30f, l0 = 0.f, l1 = 0.f;

  for (int kt = 0; kt < 16; kt++) {
    __syncthreads();   // prior compute done with K/V smem
    #pragma unroll
    for (int i = 0; i < 2; i++) {
      int u = tid + i*256;
      int r = u >> 3, c = u & 7;
      size_t gk = (rowbase + kt*64 + r) * QKVN;
      uint32_t so = r*AT_ROWB + c*16;
      cp16(sb + AT_KH + so, qkvh + gk + kcol + c*8);
      cp16(sb + AT_KL + so, qkvl + gk + kcol + c*8);
      cp16(sb + AT_VH + so, qkvh + gk + vcol + c*8);
      cp16(sb + AT_VL + so, qkvl + gk + vcol + c*8);
    }
    cp_commit();
    cp_wait<0>();
    __syncthreads();

    // S = Q K^T (split-3)
    float S[8][4];
    #pragma unroll
    for (int i = 0; i < 8; i++)
      #pragma unroll
      for (int j = 0; j < 4; j++) S[i][j] = 0.f;
    #pragma unroll
    for (int kk = 0; kk < 4; kk++) {
      uint32_t kb = kk*32;
      uint32_t ah[4], al[4];
      ldsm4(ah, sb + AT_Q  + aoff + kb);
      ldsm4(al, sb + AT_QL + aoff + kb);
      #pragma unroll
      for (int g = 0; g < 4; g++) {
        uint32_t kh[4], kl[4];
        ldsm4(kh, sb + AT_KH + kboff + g*16*AT_ROWB + kb);
        ldsm4(kl, sb + AT_KL + kboff + g*16*AT_ROWB + kb);
        #pragma unroll
        for (int t = 0; t < 2; t++) {
          float* c = S[g*2 + t];
          mma_f16(c, ah, kl + t*2);
          mma_f16(c, al, kh + t*2);
          mma_f16(c, ah, kh + t*2);
        }
      }
    }

    // online softmax (rows lane>>2 and +8)
    float mx0 = -1e30f, mx1 = -1e30f;
    #pragma unroll
    for (int nt = 0; nt < 8; nt++) {
      mx0 = fmaxf(mx0, fmaxf(S[nt][0], S[nt][1]));
      mx1 = fmaxf(mx1, fmaxf(S[nt][2], S[nt][3]));
    }
    mx0 = fmaxf(mx0, __shfl_xor_sync(0xffffffffu, mx0, 1));
    mx0 = fmaxf(mx0, __shfl_xor_sync(0xffffffffu, mx0, 2));
    mx1 = fmaxf(mx1, __shfl_xor_sync(0xffffffffu, mx1, 1));
    mx1 = fmaxf(mx1, __shfl_xor_sync(0xffffffffu, mx1, 2));
    float mn0 = fmaxf(m0, mx0), mn1 = fmaxf(m1, mx1);
    float a0 = __expf(m0 - mn0), a1 = __expf(m1 - mn1);
    float s0 = 0.f, s1 = 0.f;
    #pragma unroll
    for (int nt = 0; nt < 8; nt++) {
      S[nt][0] = __expf(S[nt][0] - mn0);
      S[nt][1] = __expf(S[nt][1] - mn0);
      S[nt][2] = __expf(S[nt][2] - mn1);
      S[nt][3] = __expf(S[nt][3] - mn1);
      s0 += S[nt][0] + S[nt][1];
      s1 += S[nt][2] + S[nt][3];
    }
    s0 += __shfl_xor_sync(0xffffffffu, s0, 1);
    s0 += __shfl_xor_sync(0xffffffffu, s0, 2);
    s1 += __shfl_xor_sync(0xffffffffu, s1, 1);
    s1 += __shfl_xor_sync(0xffffffffu, s1, 2);
    l0 = l0*a0 + s0; l1 = l1*a1 + s1;
    m0 = mn0; m1 = mn1;
    #pragma unroll
    for (int nt = 0; nt < 8; nt++) {
      O[nt][0] *= a0; O[nt][1] *= a0;
      O[nt][2] *= a1; O[nt][3] *= a1;
    }

    // O += P V (split-3); P from S regs
    #pragma unroll
    for (int kk = 0; kk < 4; kk++) {
      uint32_t ph[4], pl[4];
      #pragma unroll
      for (int half = 0; half < 2; half++) {
        float* s0p = S[kk*2 + half];
        float h00 = __half2float(__float2half_rn(s0p[0]));
        float h01 = __half2float(__float2half_rn(s0p[1]));
        float h02 = __half2float(__float2half_rn(s0p[2]));
        float h03 = __half2float(__float2half_rn(s0p[3]));
        ph[half*2 + 0] = packh2(h00, h01);
        ph[half*2 + 1] = packh2(h02, h03);
        pl[half*2 + 0] = packh2(s0p[0] - h00, s0p[1] - h01);
        pl[half*2 + 1] = packh2(s0p[2] - h02, s0p[3] - h03);
      }
      // reorder: a0=(r,k0..), a1=(r+8,k0..), a2=(r,k8..), a3=(r+8,k8..)
      uint32_t ah2[4] = {ph[0], ph[1], ph[2], ph[3]};
      uint32_t al2[4] = {pl[0], pl[1], pl[2], pl[3]};
      #pragma unroll
      for (int nb = 0; nb < 4; nb++) {
        uint32_t vh[4], vl[4];
        uint32_t va = voff + kk*16*AT_ROWB + nb*32;
        ldsm4t(vh, sb + AT_VH + va);
        ldsm4t(vl, sb + AT_VL + va);
        #pragma unroll
        for (int t = 0; t < 2; t++) {
          float* c = O[nb*2 + t];
          mma_f16(c, ah2, vl + t*2);
          mma_f16(c, al2, vh + t*2);
          mma_f16(c, ah2, vh + t*2);
        }
      }
    }
  }

  // write out hi/lo
  float inv0 = 1.0f / l0, inv1 = 1.0f / l1;
  int r0 = qt*128 + wid*16 + (lane >> 2);
  size_t ob0 = (rowbase + r0) * DIM;
  size_t ob1 = (rowbase + r0 + 8) * DIM;
  #pragma unroll
  for (int nt = 0; nt < 8; nt++) {
    int col = h*HD + nt*8 + (lane & 3)*2;
    float v0 = O[nt][0]*inv0, v1 = O[nt][1]*inv0;
    float v2 = O[nt][2]*inv1, v3 = O[nt][3]*inv1;
    float h0 = __half2float(__float2half_rn(v0)), h1 = __half2float(__float2half_rn(v1));
    float h2 = __half2float(__float2half_rn(v2)), h3 = __half2float(__float2half_rn(v3));
    *(uint32_t*)(oh + ob0 + col) = packh2(v0, v1);
    *(uint32_t*)(ol + ob0 + col) = packh2(v0 - h0, v1 - h1);
    *(uint32_t*)(oh + ob1 + col) = packh2(v2, v3);
    *(uint32_t*)(ol + ob1 + col) = packh2(v2 - h2, v3 - h3);
  }
}

// --------- transpose + fp16 split ---------
template<int WITH_LO>
__global__ void transpose_split(const float* __restrict__ in, __half* __restrict__ oh,
                                __half* __restrict__ ol, int R, int C) {
  __shared__ float t[32][33];
  size_t eo = (size_t)blockIdx.z * R * C;
  int c0 = blockIdx.x * 32, r0 = blockIdx.y * 32;
  int tx = threadIdx.x, ty = threadIdx.y;
  #pragma unroll
  for (int i = 0; i < 32; i += 8)
    t[ty + i][tx] = in[eo + (size_t)(r0 + ty + i) * C + c0 + tx];
  __syncthreads();
  #pragma unroll
  for (int i = 0; i < 32; i += 8) {
    float v = t[tx][ty + i];
    size_t o = eo + (size_t)(c0 + ty + i) * R + r0 + tx;
    __half h = __float2half_rn(v);
    oh[o] = h;
    if constexpr (WITH_LO) ol[o] = __float2half_rn(v - __half2float(h));
  }
}

// ---------------- LayerNorm ----------------
__global__ void ln_kernel(const float* __restrict__ in, const float* __restrict__ gam,
                          const float* __restrict__ bet, float* __restrict__ of,
                          __half* __restrict__ oh, __half* __restrict__ ol) {
  __shared__ float red[256];
  int row = blockIdx.x, tid = threadIdx.x;
  const float* x = in + (size_t)row * DIM;
  float v0 = x[tid], v1 = x[tid+256], v2 = x[tid+512];
  red[tid] = v0+v1+v2; __syncthreads();
  for (int o=128;o;o>>=1){ if (tid<o) red[tid]+=red[tid+o]; __syncthreads(); }
  float mean = red[0] * (1.0f/DIM);
  __syncthreads();
  float d0=v0-mean, d1=v1-mean, d2=v2-mean;
  red[tid] = d0*d0+d1*d1+d2*d2; __syncthreads();
  for (int o=128;o;o>>=1){ if (tid<o) red[tid]+=red[tid+o]; __syncthreads(); }
  float r = rsqrtf(red[0]*(1.0f/DIM) + 1e-5f);
  size_t base = (size_t)row * DIM;
  #pragma unroll
  for (int j = 0; j < 3; j++) {
    int c = tid + j*256;
    float d = (j==0) ? d0 : (j==1) ? d1 : d2;
    float v = d*r*gam[c] + bet[c];
    if (of) of[base + c] = v;
    __half h = __float2half_rn(v);
    oh[base + c] = h;
    if (ol) ol[base + c] = __float2half_rn(v - __half2float(h));
  }
}

// ---------------- Router ----------------
__global__ void zero_counts(int* c){ if (threadIdx.x < NE) c[threadIdx.x]=0; }

__global__ void router_kernel(const float* __restrict__ xln2, const float* __restrict__ Wr,
                              int* __restrict__ bucket, float* __restrict__ pairw,
                              int* __restrict__ count) {
  int gw = (int)((blockIdx.x * blockDim.x + threadIdx.x) >> 5);
  int lane = threadIdx.x & 31;
  if (gw >= NTOK) return;
  const float* x = xln2 + (size_t)gw * DIM;
  float lg[NE];
  #pragma unroll
  for (int e=0;e<NE;e++) lg[e]=0.f;
  for (int d=lane; d<DIM; d+=32) {
    float xv = x[d];
    #pragma unroll
    for (int e=0;e<NE;e++) lg[e] += xv * Wr[d*NE + e];
  }
  #pragma unroll
  for (int e=0;e<NE;e++)
    for (int off=16; off; off>>=1) lg[e] += __shfl_xor_sync(0xffffffffu, lg[e], off);
  if (lane == 0) {
    int i0 = 0;
    #pragma unroll
    for (int e=1;e<NE;e++) if (lg[e] > lg[i0]) i0 = e;
    int i1 = (i0==0) ? 1 : 0;
    #pragma unroll
    for (int e=0;e<NE;e++) { if (e==i0) continue; if (lg[e] > lg[i1]) i1 = e; }
    float w0 = 1.f / (1.f + expf(lg[i1] - lg[i0]));
    float w1 = 1.f - w0;
    int p0 = gw*2, p1 = gw*2+1;
    pairw[p0] = w0; pairw[p1] = w1;
    int q0 = atomicAdd(&count[i0], 1); bucket[i0*NPAIR + q0] = p0;
    int q1 = atomicAdd(&count[i1], 1); bucket[i1*NPAIR + q1] = p1;
  }
}

// ---------------- Combine ----------------
__global__ void combine_kernel(const float* __restrict__ x1, const float* __restrict__ slot,
                               float* __restrict__ out) {
  int idx = blockIdx.x * 256 + threadIdx.x;
  if (idx >= NTOK*DIM) return;
  int t = idx / DIM, j = idx - t*DIM;
  out[idx] = x1[idx] + slot[(size_t)(2*t)*DIM + j] + slot[(size_t)(2*t+1)*DIM + j];
}

extern "C" void kernel_launch(void* const* d_in, const int* in_sizes, int n_in,
                              void* d_out, int out_size) {
  const float* x       = (const float*)d_in[0];
  const float* Wqkv    = (const float*)d_in[1];
  const float* Wproj   = (const float*)d_in[2];
  const float* Wrouter = (const float*)d_in[3];
  const float* W1      = (const float*)d_in[4];
  const float* W2      = (const float*)d_in[5];
  const float* ln1g    = (const float*)d_in[6];
  const float* ln1b    = (const float*)d_in[7];
  const float* ln2g    = (const float*)d_in[8];
  const float* ln2b    = (const float*)d_in[9];
  float* out = (float*)d_out;

  Scratch* s = nullptr;
  cudaGetSymbolAddress((void**)&s, g_s);

  cudaFuncSetAttribute(attn_tc, cudaFuncAttributeMaxDynamicSharedMemorySize, AT_SMEM);
  cudaFuncSetAttribute(gemm_f16<0,1>, cudaFuncAttributeMaxDynamicSharedMemorySize, GSMEM_S);
  cudaFuncSetAttribute(gemm_f16<1,1>, cudaFuncAttributeMaxDynamicSharedMemorySize, GSMEM_S);
  cudaFuncSetAttribute(gemm_f16<2,0>, cudaFuncAttributeMaxDynamicSharedMemorySize, GSMEM_1);
  cudaFuncSetAttribute(gemm_f16<3,0>, cudaFuncAttributeMaxDynamicSharedMemorySize, GSMEM_1);

  dim3 tb(32, 8);
  transpose_split<1><<<dim3(QKVN/32, DIM/32, 1), tb>>>(Wqkv, s->Wqkvth, s->Wqkvtl, DIM, QKVN);
  transpose_split<1><<<dim3(DIM/32, DIM/32, 1), tb>>>(Wproj, s->Wprojth, s->Wprojtl, DIM, DIM);
  transpose_split<0><<<dim3(FFD/32, DIM/32, NE), tb>>>(W1, s->W1th, nullptr, DIM, FFD);
  transpose_split<0><<<dim3(DIM/32, FFD/32, NE), tb>>>(W2, s->W2th, nullptr, FFD, DIM);

  // x -> ln1 -> qkv(fp16 hi/lo, Q scaled) -> attention(TC) -> proj+residual -> x1
  ln_kernel<<<NTOK, 256>>>(x, ln1g, ln1b, nullptr, s->xln1h, s->xln1l);
  gemm_f16<0,1><<<dim3(QKVN/128, NTOK/128, 1), 256, GSMEM_S>>>(
      s->xln1h, s->xln1l, s->Wqkvth, s->Wqkvtl, nullptr, s->qkvh, s->qkvl,
      NTOK, QKVN, DIM, nullptr, nullptr, nullptr, nullptr);
  attn_tc<<<dim3(TSEQ/128, NH, NB), 256, AT_SMEM>>>(s->qkvh, s->qkvl, s->attnh, s->attnl);
  gemm_f16<1,1><<<dim3(DIM/128, NTOK/128, 1), 256, GSMEM_S>>>(
      s->attnh, s->attnl, s->Wprojth, s->Wprojtl, s->x1, nullptr, nullptr,
      NTOK, DIM, DIM, nullptr, nullptr, x, nullptr);

  // x1 -> ln2 -> router -> MoE -> combine
  ln_kernel<<<NTOK, 256>>>(s->x1, ln2g, ln2b, s->xln2, s->xln2h, nullptr);
  zero_counts<<<1, 32>>>(s->count);
  router_kernel<<<NTOK/8, 256>>>(s->xln2, Wrouter, s->bucket, s->pairw, s->count);
  gemm_f16<2,0><<<dim3(FFD/128, NPAIR/128, NE), 256, GSMEM_1>>>(
      s->xln2h, nullptr, s->W1th, nullptr, nullptr, s->Hh, nullptr,
      0, FFD, DIM, s->bucket, s->count, nullptr, nullptr);
  gemm_f16<3,0><<<dim3(DIM/128, NPAIR/128, NE), 256, GSMEM_1>>>(
      s->Hh, nullptr, s->W2th, nullptr, s->slot, nullptr, nullptr,
      0, DIM, FFD, s->bucket, s->count, nullptr, s->pairw);
  combine_kernel<<<(NTOK*DIM)/256, 256>>>(s->x1, s->slot, out);
}

// round 9
// speedup vs baseline: 3.2339x; 1.0420x over previous
#include <cuda_runtime.h>
#include <cuda_fp16.h>
#include <math.h>
#include <stdint.h>

#define NTOK 4096
#define DIM 768
#define QKVN (3*DIM)
#define FFD 3072
#define NE 8
#define NPAIR (NTOK*2)
#define TSEQ 1024
#define NB 4
#define NH 12
#define HD 64

// GEMM tiling: 128x128 block, BK=32 (fp16), 8 warps (4m x 2n)
#define BKE 32
#define ROWB 80
#define AREG (128*ROWB)
#define GSMEM_S (2*4*AREG)        // split:  2 stages x (Ah,Al,Bh,Bl) = 81920
#define GSMEM_1 (3*2*AREG)        // single: 3 stages x (Ah,Bh)       = 61440

// attention: Q 128x64 hi/lo + double-buffered KV (64x64 x4 regions)
#define AT_ROWB 144
#define AT_QL   (128*AT_ROWB)
#define AT_KV0  (2*128*AT_ROWB)          // 36864
#define KVBUF   (4*64*AT_ROWB)           // 36864
#define AT_SMEM (AT_KV0 + 2*KVBUF)       // 110592

struct Scratch {
  float x1[(size_t)NTOK*DIM];
  float xln2[(size_t)NTOK*DIM];
  __half qkvh[(size_t)NTOK*QKVN], qkvl[(size_t)NTOK*QKVN];
  __half xln1h[(size_t)NTOK*DIM], xln1l[(size_t)NTOK*DIM];
  __half attnh[(size_t)NTOK*DIM], attnl[(size_t)NTOK*DIM];
  __half xln2h[(size_t)NTOK*DIM];
  __half Hh[(size_t)NPAIR*FFD];
  __half Wqkvth[(size_t)QKVN*DIM], Wqkvtl[(size_t)QKVN*DIM];
  __half Wprojth[(size_t)DIM*DIM], Wprojtl[(size_t)DIM*DIM];
  __half W1th[(size_t)NE*FFD*DIM];
  __half W2th[(size_t)NE*DIM*FFD];
  float pairw[NPAIR];
  int bucket[NE*NPAIR];
  int count[NE];
};
__device__ Scratch g_s;

__device__ __forceinline__ float gelu_f(float v) {
  return 0.5f * v * (1.0f + erff(v * 0.70710678118654752f));
}
__device__ __forceinline__ uint32_t smem_u32(const void* p) {
  uint32_t a;
  asm("{ .reg .u64 t; cvta.to.shared.u64 t, %1; cvt.u32.u64 %0, t; }" : "=r"(a) : "l"(p));
  return a;
}
__device__ __forceinline__ void cp16(uint32_t dst, const void* src) {
  asm volatile("cp.async.cg.shared.global [%0], [%1], 16;\n" :: "r"(dst), "l"(src));
}
__device__ __forceinline__ void cp_commit() { asm volatile("cp.async.commit_group;\n"); }
template<int N> __device__ __forceinline__ void cp_wait() {
  asm volatile("cp.async.wait_group %0;\n" :: "n"(N));
}
__device__ __forceinline__ void ldsm4(uint32_t* r, uint32_t addr) {
  asm volatile("ldmatrix.sync.aligned.m8n8.x4.shared.b16 {%0,%1,%2,%3}, [%4];"
    : "=r"(r[0]), "=r"(r[1]), "=r"(r[2]), "=r"(r[3]) : "r"(addr));
}
__device__ __forceinline__ void ldsm4t(uint32_t* r, uint32_t addr) {
  asm volatile("ldmatrix.sync.aligned.m8n8.x4.trans.shared.b16 {%0,%1,%2,%3}, [%4];"
    : "=r"(r[0]), "=r"(r[1]), "=r"(r[2]), "=r"(r[3]) : "r"(addr));
}
__device__ __forceinline__ void mma_f16(float* c, const uint32_t* a, const uint32_t* b) {
  asm volatile(
    "mma.sync.aligned.m16n8k16.row.col.f32.f16.f16.f32 "
    "{%0,%1,%2,%3},{%4,%5,%6,%7},{%8,%9},{%0,%1,%2,%3};\n"
    : "+f"(c[0]), "+f"(c[1]), "+f"(c[2]), "+f"(c[3])
    : "r"(a[0]), "r"(a[1]), "r"(a[2]), "r"(a[3]), "r"(b[0]), "r"(b[1]));
}
__device__ __forceinline__ uint32_t packh2(float x, float y) {
  __half2 h; h.x = __float2half_rn(x); h.y = __float2half_rn(y);
  return *(uint32_t*)&h;
}

// =============== fp16 GEMM via mma.m16n8k16 + ldmatrix ===============
// SPLIT=1 (2-stage): MODE 0 qkv->fp16 hi/lo (Q scaled), MODE 1 proj+resid->f32
// SPLIT=0 (3-stage): MODE 2 MoE-up gelu->fp16, MODE 3 MoE-down atomicAdd(w*acc)->out
template<int MODE, int SPLIT>
__global__ __launch_bounds__(256, 2)
void gemm_f16(const __half* __restrict__ Ahg, const __half* __restrict__ Alg,
              const __half* __restrict__ Bhg, const __half* __restrict__ Blg,
              float* __restrict__ Cf, __half* __restrict__ Chalf, __half* __restrict__ Chalf2,
              int M, int N, int K,
              const int* __restrict__ bucket, const int* __restrict__ counts,
              const float* __restrict__ resid, const float* __restrict__ pairw)
{
  constexpr int NOPS = SPLIT ? 4 : 2;
  constexpr int STG  = SPLIT ? 2 : 3;
  constexpr int STGB = NOPS * AREG;
  extern __shared__ char dynsm[];
  __shared__ int sPair[128];

  int tid = threadIdx.x, wid = tid >> 5, lane = tid & 31;
  int e = (MODE >= 2) ? blockIdx.z : 0;
  int mcount = (MODE >= 2) ? counts[e] : M;
  int m0 = blockIdx.y * 128;
  if (m0 >= mcount) return;
  int n0 = blockIdx.x * 128;

  if constexpr (MODE >= 2) {
    Bhg += (size_t)e * K * N;
    if (tid < 128) {
      int gm = m0 + tid;
      sPair[tid] = bucket[e * NPAIR + (gm < mcount ? gm : mcount - 1)];
    }
    __syncthreads();
  }

  uint32_t sbase = smem_u32(dynsm);

  int arow[2];
  #pragma unroll
  for (int i = 0; i < 2; i++) {
    int row = (tid + i*256) >> 2;
    if constexpr (MODE == 2)      arow[i] = sPair[row] >> 1;
    else if constexpr (MODE == 3) arow[i] = sPair[row];
    else                          arow[i] = m0 + row;
  }

  auto load_chunk = [&](int stage, int k0) {
    uint32_t st = sbase + stage * STGB;
    #pragma unroll
    for (int i = 0; i < 2; i++) {
      int u = tid + i*256;
      int row = u >> 2, c = u & 3;
      uint32_t so = row*ROWB + c*16;
      size_t go = (size_t)arow[i] * K + k0 + c*8;
      cp16(st + so, Ahg + go);
      if constexpr (SPLIT) cp16(st + AREG + so, Alg + go);
    }
    #pragma unroll
    for (int i = 0; i < 2; i++) {
      int u = tid + i*256;
      int row = u >> 2, c = u & 3;
      uint32_t so = row*ROWB + c*16;
      size_t go = (size_t)(n0 + row) * K + k0 + c*8;
      cp16(st + (SPLIT ? 2 : 1)*AREG + so, Bhg + go);
      if constexpr (SPLIT) cp16(st + 3*AREG + so, Blg + go);
    }
    cp_commit();
  };

  int wm = wid >> 1, wn = wid & 1;
  uint32_t aoff = (uint32_t)((wm*32 + (lane & 15))*ROWB + (lane >> 4)*16);
  uint32_t boff = (uint32_t)((wn*64 + (lane & 7) + ((lane >> 4) << 3))*ROWB +
                             ((lane >> 3) & 1)*16);

  float acc[2][8][4];
  #pragma unroll
  for (int i = 0; i < 2; i++)
    #pragma unroll
    for (int j = 0; j < 8; j++)
      #pragma unroll
      for (int q = 0; q < 4; q++) acc[i][j][q] = 0.f;

  auto compute = [&](int stage) {
    uint32_t st = sbase + stage * STGB;
    uint32_t bbase = st + (SPLIT ? 2 : 1)*AREG;
    #pragma unroll
    for (int ks = 0; ks < 2; ks++) {
      uint32_t kb = ks * 32;
      uint32_t ah[2][4], al[2][4];
      ldsm4(ah[0], st + aoff + kb);
      ldsm4(ah[1], st + aoff + 16*ROWB + kb);
      if constexpr (SPLIT) {
        ldsm4(al[0], st + AREG + aoff + kb);
        ldsm4(al[1], st + AREG + aoff + 16*ROWB + kb);
      }
      #pragma unroll
      for (int g = 0; g < 4; g++) {
        uint32_t bh[4], bl[4];
        ldsm4(bh, bbase + boff + g*16*ROWB + kb);
        if constexpr (SPLIT) ldsm4(bl, st + 3*AREG + boff + g*16*ROWB + kb);
        #pragma unroll
        for (int t = 0; t < 2; t++) {
          #pragma unroll
          for (int mt = 0; mt < 2; mt++) {
            float* c = acc[mt][g*2 + t];
            if constexpr (SPLIT) {
              mma_f16(c, ah[mt], bl + t*2);
              mma_f16(c, al[mt], bh + t*2);
            }
            mma_f16(c, ah[mt], bh + t*2);
          }
        }
      }
    }
  };

  int nkt = K / BKE;
  load_chunk(0, 0);
  if (STG == 3 && nkt > 1) load_chunk(1, BKE);
  for (int kt = 0; kt < nkt; kt++) {
    if (STG == 3 && kt + 2 < nkt) cp_wait<1>(); else cp_wait<0>();
    __syncthreads();
    int nx = kt + (STG == 3 ? 2 : 1);
    if (nx < nkt) load_chunk(nx % STG, nx * BKE);
    compute(kt % STG);
  }

  #pragma unroll
  for (int mt = 0; mt < 2; mt++) {
    #pragma unroll
    for (int half = 0; half < 2; half++) {
      int rl = wm*32 + mt*16 + (lane >> 2) + half*8;
      int gmi = m0 + rl;
      if (gmi < mcount) {
        int crow; float w = 1.f;
        if constexpr (MODE >= 2) {
          int pr = sPair[rl];
          crow = pr;
          if constexpr (MODE == 3) w = pairw[pr];
        } else crow = gmi;
        #pragma unroll
        for (int nt = 0; nt < 8; nt++) {
          int col = n0 + wn*64 + nt*8 + (lane & 3)*2;
          float v0 = acc[mt][nt][half*2 + 0];
          float v1 = acc[mt][nt][half*2 + 1];
          if constexpr (MODE == 0) {
            float sc = (col < DIM) ? 0.125f : 1.0f;
            v0 *= sc; v1 *= sc;
            __half h0 = __float2half_rn(v0), h1 = __float2half_rn(v1);
            __half2 hv; hv.x = h0; hv.y = h1;
            __half2 lv;
            lv.x = __float2half_rn(v0 - __half2float(h0));
            lv.y = __float2half_rn(v1 - __half2float(h1));
            *(__half2*)(Chalf + (size_t)crow * N + col) = hv;
            *(__half2*)(Chalf2 + (size_t)crow * N + col) = lv;
          } else if constexpr (MODE == 1) {
            const float* rp = resid + (size_t)gmi * N + col;
            *(float2*)(Cf + (size_t)crow * N + col) = make_float2(v0 + rp[0], v1 + rp[1]);
          } else if constexpr (MODE == 2) {
            __half2 hv;
            hv.x = __float2half_rn(gelu_f(v0));
            hv.y = __float2half_rn(gelu_f(v1));
            *(__half2*)(Chalf + (size_t)crow * N + col) = hv;
          } else {
            float* cp = Cf + (size_t)(crow >> 1) * N + col;   // token row of out
            atomicAdd(cp + 0, v0 * w);
            atomicAdd(cp + 1, v1 * w);
          }
        }
      }
    }
  }
}

// ============ Tensor-core flash attention (fp16 split-3, fp32 softmax) ============
__global__ __launch_bounds__(256, 2)
void attn_tc(const __half* __restrict__ qkvh, const __half* __restrict__ qkvl,
             __half* __restrict__ oh, __half* __restrict__ ol) {
  extern __shared__ char dynsm[];
  uint32_t sb = smem_u32(dynsm);
  int tid = threadIdx.x, wid = tid >> 5, lane = tid & 31;
  int qt = blockIdx.x, h = blockIdx.y, b = blockIdx.z;
  int qcol = h*HD, kcol = DIM + h*HD, vcol = 2*DIM + h*HD;
  size_t rowbase = (size_t)b * TSEQ;

  auto loadKV = [&](int kt, int buf) {
    uint32_t kb = sb + AT_KV0 + buf * KVBUF;
    #pragma unroll
    for (int i = 0; i < 2; i++) {
      int u = tid + i*256;
      int r = u >> 3, c = u & 7;
      size_t gk = (rowbase + kt*64 + r) * QKVN;
      uint32_t so = r*AT_ROWB + c*16;
      cp16(kb + so,                    qkvh + gk + kcol + c*8);
      cp16(kb + 64*AT_ROWB + so,       qkvl + gk + kcol + c*8);
      cp16(kb + 2*64*AT_ROWB + so,     qkvh + gk + vcol + c*8);
      cp16(kb + 3*64*AT_ROWB + so,     qkvl + gk + vcol + c*8);
    }
    cp_commit();
  };

  // prologue: Q tile + KV(0) in one group
  #pragma unroll
  for (int i = 0; i < 4; i++) {
    int u = tid + i*256;
    int r = u >> 3, c = u & 7;
    size_t go = (rowbase + qt*128 + r) * QKVN + qcol + c*8;
    uint32_t so = r*AT_ROWB + c*16;
    cp16(sb + so,         qkvh + go);
    cp16(sb + AT_QL + so, qkvl + go);
  }
  loadKV(0, 0);

  uint32_t aoff = (uint32_t)((wid*16 + (lane & 15))*AT_ROWB + (lane >> 4)*16);
  uint32_t kboff = (uint32_t)(((lane & 7) + ((lane >> 4) << 3))*AT_ROWB + ((lane >> 3) & 1)*16);
  uint32_t voff = (uint32_t)((lane & 15)*AT_ROWB + (lane >> 4)*16);

  float O[8][4];
  #pragma unroll
  for (int i = 0; i < 8; i++)
    #pragma unroll
    for (int j = 0; j < 4; j++) O[i][j] = 0.f;
  float m0 = -1e30f, m1 = -1e30f, l0 = 0.f, l1 = 0.f;

  for (int kt = 0; kt < 16; kt++) {
    cp_wait<0>();
    __syncthreads();
    if (kt < 15) loadKV(kt + 1, (kt + 1) & 1);
    uint32_t kvb = sb + AT_KV0 + (kt & 1) * KVBUF;
    uint32_t KH = kvb, KL = kvb + 64*AT_ROWB, VH = kvb + 2*64*AT_ROWB, VL = kvb + 3*64*AT_ROWB;

    // S = Q K^T (split-3)
    float S[8][4];
    #pragma unroll
    for (int i = 0; i < 8; i++)
      #pragma unroll
      for (int j = 0; j < 4; j++) S[i][j] = 0.f;
    #pragma unroll
    for (int kk = 0; kk < 4; kk++) {
      uint32_t kb = kk*32;
      uint32_t ah[4], al[4];
      ldsm4(ah, sb + aoff + kb);
      ldsm4(al, sb + AT_QL + aoff + kb);
      #pragma unroll
      for (int g = 0; g < 4; g++) {
        uint32_t kh[4], kl[4];
        ldsm4(kh, KH + kboff + g*16*AT_ROWB + kb);
        ldsm4(kl, KL + kboff + g*16*AT_ROWB + kb);
        #pragma unroll
        for (int t = 0; t < 2; t++) {
          float* c = S[g*2 + t];
          mma_f16(c, ah, kl + t*2);
          mma_f16(c, al, kh + t*2);
          mma_f16(c, ah, kh + t*2);
        }
      }
    }

    // online softmax
    float mx0 = -1e30f, mx1 = -1e30f;
    #pragma unroll
    for (int nt = 0; nt < 8; nt++) {
      mx0 = fmaxf(mx0, fmaxf(S[nt][0], S[nt][1]));
      mx1 = fmaxf(mx1, fmaxf(S[nt][2], S[nt][3]));
    }
    mx0 = fmaxf(mx0, __shfl_xor_sync(0xffffffffu, mx0, 1));
    mx0 = fmaxf(mx0, __shfl_xor_sync(0xffffffffu, mx0, 2));
    mx1 = fmaxf(mx1, __shfl_xor_sync(0xffffffffu, mx1, 1));
    mx1 = fmaxf(mx1, __shfl_xor_sync(0xffffffffu, mx1, 2));
    float mn0 = fmaxf(m0, mx0), mn1 = fmaxf(m1, mx1);
    float a0 = __expf(m0 - mn0), a1 = __expf(m1 - mn1);
    float s0 = 0.f, s1 = 0.f;
    #pragma unroll
    for (int nt = 0; nt < 8; nt++) {
      S[nt][0] = __expf(S[nt][0] - mn0);
      S[nt][1] = __expf(S[nt][1] - mn0);
      S[nt][2] = __expf(S[nt][2] - mn1);
      S[nt][3] = __expf(S[nt][3] - mn1);
      s0 += S[nt][0] + S[nt][1];
      s1 += S[nt][2] + S[nt][3];
    }
    s0 += __shfl_xor_sync(0xffffffffu, s0, 1);
    s0 += __shfl_xor_sync(0xffffffffu, s0, 2);
    s1 += __shfl_xor_sync(0xffffffffu, s1, 1);
    s1 += __shfl_xor_sync(0xffffffffu, s1, 2);
    l0 = l0*a0 + s0; l1 = l1*a1 + s1;
    m0 = mn0; m1 = mn1;
    #pragma unroll
    for (int nt = 0; nt < 8; nt++) {
      O[nt][0] *= a0; O[nt][1] *= a0;
      O[nt][2] *= a1; O[nt][3] *= a1;
    }

    // O += P V (split-3)
    #pragma unroll
    for (int kk = 0; kk < 4; kk++) {
      uint32_t ph[4], pl[4];
      #pragma unroll
      for (int half = 0; half < 2; half++) {
        float* sp = S[kk*2 + half];
        float h00 = __half2float(__float2half_rn(sp[0]));
        float h01 = __half2float(__float2half_rn(sp[1]));
        float h02 = __half2float(__float2half_rn(sp[2]));
        float h03 = __half2float(__float2half_rn(sp[3]));
        ph[half*2 + 0] = packh2(h00, h01);
        ph[half*2 + 1] = packh2(h02, h03);
        pl[half*2 + 0] = packh2(sp[0] - h00, sp[1] - h01);
        pl[half*2 + 1] = packh2(sp[2] - h02, sp[3] - h03);
      }
      #pragma unroll
      for (int nb = 0; nb < 4; nb++) {
        uint32_t vh[4], vl[4];
        uint32_t va = voff + kk*16*AT_ROWB + nb*32;
        ldsm4t(vh, VH + va);
        ldsm4t(vl, VL + va);
        #pragma unroll
        for (int t = 0; t < 2; t++) {
          float* c = O[nb*2 + t];
          mma_f16(c, ph, vl + t*2);
          mma_f16(c, pl, vh + t*2);
          mma_f16(c, ph, vh + t*2);
        }
      }
    }
  }

  float inv0 = 1.0f / l0, inv1 = 1.0f / l1;
  int r0 = qt*128 + wid*16 + (lane >> 2);
  size_t ob0 = (rowbase + r0) * DIM;
  size_t ob1 = (rowbase + r0 + 8) * DIM;
  #pragma unroll
  for (int nt = 0; nt < 8; nt++) {
    int col = h*HD + nt*8 + (lane & 3)*2;
    float v0 = O[nt][0]*inv0, v1 = O[nt][1]*inv0;
    float v2 = O[nt][2]*inv1, v3 = O[nt][3]*inv1;
    float h0 = __half2float(__float2half_rn(v0)), h1 = __half2float(__float2half_rn(v1));
    float h2 = __half2float(__float2half_rn(v2)), h3 = __half2float(__float2half_rn(v3));
    *(uint32_t*)(oh + ob0 + col) = packh2(v0, v1);
    *(uint32_t*)(ol + ob0 + col) = packh2(v0 - h0, v1 - h1);
    *(uint32_t*)(oh + ob1 + col) = packh2(v2, v3);
    *(uint32_t*)(ol + ob1 + col) = packh2(v2 - h2, v3 - h3);
  }
}

// --------- transpose + fp16 split (vectorized half2 stores) ---------
template<int WITH_LO>
__global__ void transpose_split(const float* __restrict__ in, __half* __restrict__ oh,
                                __half* __restrict__ ol, int R, int C) {
  __shared__ float t[32][33];
  size_t eo = (size_t)blockIdx.z * R * C;
  int c0 = blockIdx.x * 32, r0 = blockIdx.y * 32;
  int tx = threadIdx.x, ty = threadIdx.y;
  #pragma unroll
  for (int i = 0; i < 32; i += 8)
    t[ty + i][tx] = in[eo + (size_t)(r0 + ty + i) * C + c0 + tx];
  __syncthreads();
  int txl = tx & 15, txh = tx >> 4;
  #pragma unroll
  for (int i = 0; i < 32; i += 16) {
    int orow = ty*2 + txh + i;
    float v0 = t[2*txl][orow], v1 = t[2*txl + 1][orow];
    size_t o = eo + (size_t)(c0 + orow) * R + r0 + 2*txl;
    __half h0 = __float2half_rn(v0), h1 = __float2half_rn(v1);
    __half2 hv; hv.x = h0; hv.y = h1;
    *(__half2*)(oh + o) = hv;
    if constexpr (WITH_LO) {
      __half2 lv;
      lv.x = __float2half_rn(v0 - __half2float(h0));
      lv.y = __float2half_rn(v1 - __half2float(h1));
      *(__half2*)(ol + o) = lv;
    }
  }
}

// ---------------- LayerNorm (f32 opt + fp16 hi (+lo) + optional raw copy) ----------------
__global__ void ln_kernel(const float* __restrict__ in, const float* __restrict__ gam,
                          const float* __restrict__ bet, float* __restrict__ of,
                          __half* __restrict__ oh, __half* __restrict__ ol,
                          float* __restrict__ ocopy) {
  __shared__ float red[256];
  int row = blockIdx.x, tid = threadIdx.x;
  const float* x = in + (size_t)row * DIM;
  float v0 = x[tid], v1 = x[tid+256], v2 = x[tid+512];
  red[tid] = v0+v1+v2; __syncthreads();
  for (int o=128;o;o>>=1){ if (tid<o) red[tid]+=red[tid+o]; __syncthreads(); }
  float mean = red[0] * (1.0f/DIM);
  __syncthreads();
  float d0=v0-mean, d1=v1-mean, d2=v2-mean;
  red[tid] = d0*d0+d1*d1+d2*d2; __syncthreads();
  for (int o=128;o;o>>=1){ if (tid<o) red[tid]+=red[tid+o]; __syncthreads(); }
  float r = rsqrtf(red[0]*(1.0f/DIM) + 1e-5f);
  size_t base = (size_t)row * DIM;
  #pragma unroll
  for (int j = 0; j < 3; j++) {
    int c = tid + j*256;
    float raw = (j==0) ? v0 : (j==1) ? v1 : v2;
    float d = (j==0) ? d0 : (j==1) ? d1 : d2;
    float v = d*r*gam[c] + bet[c];
    if (of) of[base + c] = v;
    if (ocopy) ocopy[base + c] = raw;
    __half h = __float2half_rn(v);
    oh[base + c] = h;
    if (ol) ol[base + c] = __float2half_rn(v - __half2float(h));
  }
}

// ---------------- Router ----------------
__global__ void zero_counts(int* c){ if (threadIdx.x < NE) c[threadIdx.x]=0; }

__global__ void router_kernel(const float* __restrict__ xln2, const float* __restrict__ Wr,
                              int* __restrict__ bucket, float* __restrict__ pairw,
                              int* __restrict__ count) {
  int gw = (int)((blockIdx.x * blockDim.x + threadIdx.x) >> 5);
  int lane = threadIdx.x & 31;
  if (gw >= NTOK) return;
  const float* x = xln2 + (size_t)gw * DIM;
  float lg[NE];
  #pragma unroll
  for (int e=0;e<NE;e++) lg[e]=0.f;
  for (int d=lane; d<DIM; d+=32) {
    float xv = x[d];
    #pragma unroll
    for (int e=0;e<NE;e++) lg[e] += xv * Wr[d*NE + e];
  }
  #pragma unroll
  for (int e=0;e<NE;e++)
    for (int off=16; off; off>>=1) lg[e] += __shfl_xor_sync(0xffffffffu, lg[e], off);
  if (lane == 0) {
    int i0 = 0;
    #pragma unroll
    for (int e=1;e<NE;e++) if (lg[e] > lg[i0]) i0 = e;
    int i1 = (i0==0) ? 1 : 0;
    #pragma unroll
    for (int e=0;e<NE;e++) { if (e==i0) continue; if (lg[e] > lg[i1]) i1 = e; }
    float w0 = 1.f / (1.f + expf(lg[i1] - lg[i0]));
    float w1 = 1.f - w0;
    int p0 = gw*2, p1 = gw*2+1;
    pairw[p0] = w0; pairw[p1] = w1;
    int q0 = atomicAdd(&count[i0], 1); bucket[i0*NPAIR + q0] = p0;
    int q1 = atomicAdd(&count[i1], 1); bucket[i1*NPAIR + q1] = p1;
  }
}

extern "C" void kernel_launch(void* const* d_in, const int* in_sizes, int n_in,
                              void* d_out, int out_size) {
  const float* x       = (const float*)d_in[0];
  const float* Wqkv    = (const float*)d_in[1];
  const float* Wproj   = (const float*)d_in[2];
  const float* Wrouter = (const float*)d_in[3];
  const float* W1      = (const float*)d_in[4];
  const float* W2      = (const float*)d_in[5];
  const float* ln1g    = (const float*)d_in[6];
  const float* ln1b    = (const float*)d_in[7];
  const float* ln2g    = (const float*)d_in[8];
  const float* ln2b    = (const float*)d_in[9];
  float* out = (float*)d_out;

  Scratch* s = nullptr;
  cudaGetSymbolAddress((void**)&s, g_s);

  cudaFuncSetAttribute(attn_tc, cudaFuncAttributeMaxDynamicSharedMemorySize, AT_SMEM);
  cudaFuncSetAttribute(gemm_f16<0,1>, cudaFuncAttributeMaxDynamicSharedMemorySize, GSMEM_S);
  cudaFuncSetAttribute(gemm_f16<1,1>, cudaFuncAttributeMaxDynamicSharedMemorySize, GSMEM_S);
  cudaFuncSetAttribute(gemm_f16<2,0>, cudaFuncAttributeMaxDynamicSharedMemorySize, GSMEM_1);
  cudaFuncSetAttribute(gemm_f16<3,0>, cudaFuncAttributeMaxDynamicSharedMemorySize, GSMEM_1);

  dim3 tb(32, 8);
  transpose_split<1><<<dim3(QKVN/32, DIM/32, 1), tb>>>(Wqkv, s->Wqkvth, s->Wqkvtl, DIM, QKVN);
  transpose_split<1><<<dim3(DIM/32, DIM/32, 1), tb>>>(Wproj, s->Wprojth, s->Wprojtl, DIM, DIM);
  transpose_split<0><<<dim3(FFD/32, DIM/32, NE), tb>>>(W1, s->W1th, nullptr, DIM, FFD);
  transpose_split<0><<<dim3(DIM/32, FFD/32, NE), tb>>>(W2, s->W2th, nullptr, FFD, DIM);

  // x -> ln1 -> qkv(fp16 hi/lo, Q scaled) -> attention(TC) -> proj+residual -> x1
  ln_kernel<<<NTOK, 256>>>(x, ln1g, ln1b, nullptr, s->xln1h, s->xln1l, nullptr);
  gemm_f16<0,1><<<dim3(QKVN/128, NTOK/128, 1), 256, GSMEM_S>>>(
      s->xln1h, s->xln1l, s->Wqkvth, s->Wqkvtl, nullptr, s->qkvh, s->qkvl,
      NTOK, QKVN, DIM, nullptr, nullptr, nullptr, nullptr);
  attn_tc<<<dim3(TSEQ/128, NH, NB), 256, AT_SMEM>>>(s->qkvh, s->qkvl, s->attnh, s->attnl);
  gemm_f16<1,1><<<dim3(DIM/128, NTOK/128, 1), 256, GSMEM_S>>>(
      s->attnh, s->attnl, s->Wprojth, s->Wprojtl, s->x1, nullptr, nullptr,
      NTOK, DIM, DIM, nullptr, nullptr, x, nullptr);

  // x1 -> ln2 (also copies x1 into out) -> router -> MoE (down accumulates into out)
  ln_kernel<<<NTOK, 256>>>(s->x1, ln2g, ln2b, s->xln2, s->xln2h, nullptr, out);
  zero_counts<<<1, 32>>>(s->count);
  router_kernel<<<NTOK/8, 256>>>(s->xln2, Wrouter, s->bucket, s->pairw, s->count);
  gemm_f16<2,0><<<dim3(FFD/128, NPAIR/128, NE), 256, GSMEM_1>>>(
      s->xln2h, nullptr, s->W1th, nullptr, nullptr, s->Hh, nullptr,
      0, FFD, DIM, s->bucket, s->count, nullptr, nullptr);
  gemm_f16<3,0><<<dim3(DIM/128, NPAIR/128, NE), 256, GSMEM_1>>>(
      s->Hh, nullptr, s->W2th, nullptr, out, nullptr, nullptr,
      0, DIM, FFD, s->bucket, s->count, nullptr, s->pairw);
}

// round 10
// speedup vs baseline: 3.5434x; 1.0957x over previous
#include <cuda_runtime.h>
#include <cuda_fp16.h>
#include <math.h>
#include <stdint.h>

#define NTOK 4096
#define DIM 768
#define QKVN (3*DIM)
#define FFD 3072
#define NE 8
#define NPAIR (NTOK*2)
#define TSEQ 1024
#define NB 4
#define NH 12
#define HD 64

#define BKE 32

// split GEMM: swizzled 64B rows, 3 stages x (Ah,Al,Bh,Bl)
#define SAREG 8192                      // 128 rows x 64B
#define SSTGB (4*SAREG)                 // 32768
#define GSMEM_SPLIT (3*SSTGB)           // 98304

// MoE GEMM: A 80B rows + B trans [k][n] 272B rows, 4 stages
#define MAREG 10240                     // 128 x 80
#define MBREG 8704                      // 32 x 272
#define MSTGB (MAREG + MBREG)           // 18944
#define GSMEM_MOE (4*MSTGB)             // 75776

// attention: Q 128x64 hi/lo + double-buffered KV
#define AT_ROWB 144
#define AT_QL   (128*AT_ROWB)
#define AT_KV0  (2*128*AT_ROWB)
#define KVBUF   (4*64*AT_ROWB)
#define AT_SMEM (AT_KV0 + 2*KVBUF)      // 110592

struct Scratch {
  float x1[(size_t)NTOK*DIM];
  float xln2[(size_t)NTOK*DIM];
  __half qkvh[(size_t)NTOK*QKVN], qkvl[(size_t)NTOK*QKVN];
  __half xln1h[(size_t)NTOK*DIM], xln1l[(size_t)NTOK*DIM];
  __half attnh[(size_t)NTOK*DIM], attnl[(size_t)NTOK*DIM];
  __half xln2h[(size_t)NTOK*DIM];
  __half Hh[(size_t)NPAIR*FFD];
  __half Wqkvth[(size_t)QKVN*DIM], Wqkvtl[(size_t)QKVN*DIM];
  __half Wprojth[(size_t)DIM*DIM], Wprojtl[(size_t)DIM*DIM];
  __half W1h[(size_t)NE*DIM*FFD];       // native [e][k][n]
  __half W2h[(size_t)NE*FFD*DIM];       // native [e][k][n]
  float pairw[NPAIR];
  int bucket[NE*NPAIR];
  int count[NE];
};
__device__ Scratch g_s;

__device__ __forceinline__ float gelu_f(float v) {
  return 0.5f * v * (1.0f + erff(v * 0.70710678118654752f));
}
__device__ __forceinline__ uint32_t smem_u32(const void* p) {
  uint32_t a;
  asm("{ .reg .u64 t; cvta.to.shared.u64 t, %1; cvt.u32.u64 %0, t; }" : "=r"(a) : "l"(p));
  return a;
}
__device__ __forceinline__ void cp16(uint32_t dst, const void* src) {
  asm volatile("cp.async.cg.shared.global [%0], [%1], 16;\n" :: "r"(dst), "l"(src));
}
__device__ __forceinline__ void cp_commit() { asm volatile("cp.async.commit_group;\n"); }
template<int N> __device__ __forceinline__ void cp_wait() {
  asm volatile("cp.async.wait_group %0;\n" :: "n"(N));
}
__device__ __forceinline__ void ldsm4(uint32_t* r, uint32_t addr) {
  asm volatile("ldmatrix.sync.aligned.m8n8.x4.shared.b16 {%0,%1,%2,%3}, [%4];"
    : "=r"(r[0]), "=r"(r[1]), "=r"(r[2]), "=r"(r[3]) : "r"(addr));
}
__device__ __forceinline__ void ldsm4t(uint32_t* r, uint32_t addr) {
  asm volatile("ldmatrix.sync.aligned.m8n8.x4.trans.shared.b16 {%0,%1,%2,%3}, [%4];"
    : "=r"(r[0]), "=r"(r[1]), "=r"(r[2]), "=r"(r[3]) : "r"(addr));
}
__device__ __forceinline__ void mma_f16(float* c, const uint32_t* a, const uint32_t* b) {
  asm volatile(
    "mma.sync.aligned.m16n8k16.row.col.f32.f16.f16.f32 "
    "{%0,%1,%2,%3},{%4,%5,%6,%7},{%8,%9},{%0,%1,%2,%3};\n"
    : "+f"(c[0]), "+f"(c[1]), "+f"(c[2]), "+f"(c[3])
    : "r"(a[0]), "r"(a[1]), "r"(a[2]), "r"(a[3]), "r"(b[0]), "r"(b[1]));
}
__device__ __forceinline__ uint32_t packh2(float x, float y) {
  __half2 h; h.x = __float2half_rn(x); h.y = __float2half_rn(y);
  return *(uint32_t*)&h;
}
// swizzled offset within a 128x64B operand region: 16B segment c in row
__device__ __forceinline__ uint32_t swz(int row, int c) {
  return (uint32_t)(row*64 + ((c ^ ((row >> 1) & 3)) << 4));
}

// =============== split-3 fp16 GEMM (router-safe path), swizzled, 3-stage ===============
// MODE 0: qkv = A@B -> fp16 hi/lo (Q scaled 0.125)   MODE 1: x1 = A@B + resid -> f32
template<int MODE>
__global__ __launch_bounds__(256, 2)
void gemm_split(const __half* __restrict__ Ahg, const __half* __restrict__ Alg,
                const __half* __restrict__ Bhg, const __half* __restrict__ Blg,
                float* __restrict__ Cf, __half* __restrict__ Chalf, __half* __restrict__ Chalf2,
                int M, int N, int K, const float* __restrict__ resid)
{
  extern __shared__ char dynsm[];
  int tid = threadIdx.x, wid = tid >> 5, lane = tid & 31;
  int m0 = blockIdx.y * 128;
  int n0 = blockIdx.x * 128;
  uint32_t sbase = smem_u32(dynsm);

  auto load_chunk = [&](int stage, int k0) {
    uint32_t st = sbase + stage * SSTGB;
    #pragma unroll
    for (int i = 0; i < 2; i++) {
      int u = tid + i*256;
      int row = u >> 2, c = u & 3;
      uint32_t so = swz(row, c);
      size_t go = (size_t)(m0 + row) * K + k0 + c*8;
      cp16(st + so,         Ahg + go);
      cp16(st + SAREG + so, Alg + go);
    }
    #pragma unroll
    for (int i = 0; i < 2; i++) {
      int u = tid + i*256;
      int row = u >> 2, c = u & 3;
      uint32_t so = swz(row, c);
      size_t go = (size_t)(n0 + row) * K + k0 + c*8;
      cp16(st + 2*SAREG + so, Bhg + go);
      cp16(st + 3*SAREG + so, Blg + go);
    }
    cp_commit();
  };

  int wm = wid >> 1, wn = wid & 1;
  int arow = wm*32 + (lane & 15);
  int acs  = (lane >> 4);
  int brow = wn*64 + (lane & 7) + ((lane >> 4) << 3);
  int bcs  = (lane >> 3) & 1;

  float acc[2][8][4];
  #pragma unroll
  for (int i = 0; i < 2; i++)
    #pragma unroll
    for (int j = 0; j < 8; j++)
      #pragma unroll
      for (int q = 0; q < 4; q++) acc[i][j][q] = 0.f;

  auto compute = [&](int stage) {
    uint32_t st = sbase + stage * SSTGB;
    #pragma unroll
    for (int ks = 0; ks < 2; ks++) {
      uint32_t ah[2][4], al[2][4];
      ldsm4(ah[0], st +         swz(arow,      acs + ks*2));
      ldsm4(ah[1], st +         swz(arow + 16, acs + ks*2));
      ldsm4(al[0], st + SAREG + swz(arow,      acs + ks*2));
      ldsm4(al[1], st + SAREG + swz(arow + 16, acs + ks*2));
      #pragma unroll
      for (int g = 0; g < 4; g++) {
        uint32_t bh[4], bl[4];
        ldsm4(bh, st + 2*SAREG + swz(brow + g*16, bcs + ks*2));
        ldsm4(bl, st + 3*SAREG + swz(brow + g*16, bcs + ks*2));
        #pragma unroll
        for (int t = 0; t < 2; t++) {
          #pragma unroll
          for (int mt = 0; mt < 2; mt++) {
            float* c = acc[mt][g*2 + t];
            mma_f16(c, ah[mt], bl + t*2);
            mma_f16(c, al[mt], bh + t*2);
            mma_f16(c, ah[mt], bh + t*2);
          }
        }
      }
    }
  };

  int nkt = K / BKE;
  load_chunk(0, 0);
  if (nkt > 1) load_chunk(1, BKE);
  for (int kt = 0; kt < nkt; kt++) {
    if (kt + 1 < nkt) cp_wait<1>(); else cp_wait<0>();
    __syncthreads();
    if (kt + 2 < nkt) load_chunk((kt + 2) % 3, (kt + 2) * BKE);
    compute(kt % 3);
  }

  #pragma unroll
  for (int mt = 0; mt < 2; mt++) {
    #pragma unroll
    for (int half = 0; half < 2; half++) {
      int gmi = m0 + wm*32 + mt*16 + (lane >> 2) + half*8;
      #pragma unroll
      for (int nt = 0; nt < 8; nt++) {
        int col = n0 + wn*64 + nt*8 + (lane & 3)*2;
        float v0 = acc[mt][nt][half*2 + 0];
        float v1 = acc[mt][nt][half*2 + 1];
        if constexpr (MODE == 0) {
          float sc = (col < DIM) ? 0.125f : 1.0f;
          v0 *= sc; v1 *= sc;
          __half h0 = __float2half_rn(v0), h1 = __float2half_rn(v1);
          __half2 hv; hv.x = h0; hv.y = h1;
          __half2 lv;
          lv.x = __float2half_rn(v0 - __half2float(h0));
          lv.y = __float2half_rn(v1 - __half2float(h1));
          *(__half2*)(Chalf + (size_t)gmi * N + col) = hv;
          *(__half2*)(Chalf2 + (size_t)gmi * N + col) = lv;
        } else {
          const float* rp = resid + (size_t)gmi * N + col;
          *(float2*)(Cf + (size_t)gmi * N + col) = make_float2(v0 + rp[0], v1 + rp[1]);
        }
      }
    }
  }
}

// =============== MoE fp16 GEMM, native [k][n] weights via ldsm4t, 4-stage ===============
// MODE 2: H[pair] = gelu(A[tok]@W1[e]) -> fp16    MODE 3: out[tok] += w*(H[pair]@W2[e])
template<int MODE>
__global__ __launch_bounds__(256, 2)
void gemm_moe(const __half* __restrict__ Ahg, const __half* __restrict__ Bhg,
              float* __restrict__ Cf, __half* __restrict__ Chalf,
              int N, int K,
              const int* __restrict__ bucket, const int* __restrict__ counts,
              const float* __restrict__ pairw)
{
  extern __shared__ char dynsm[];
  __shared__ int sPair[128];
  int tid = threadIdx.x, wid = tid >> 5, lane = tid & 31;
  int e = blockIdx.z;
  int mcount = counts[e];
  int m0 = blockIdx.y * 128;
  if (m0 >= mcount) return;
  int n0 = blockIdx.x * 128;
  Bhg += (size_t)e * K * N;
  if (tid < 128) {
    int gm = m0 + tid;
    sPair[tid] = bucket[e * NPAIR + (gm < mcount ? gm : mcount - 1)];
  }
  __syncthreads();

  uint32_t sbase = smem_u32(dynsm);

  int arow[2];
  #pragma unroll
  for (int i = 0; i < 2; i++) {
    int row = (tid + i*256) >> 2;
    arow[i] = (MODE == 2) ? (sPair[row] >> 1) : sPair[row];
  }

  auto load_chunk = [&](int stage, int k0) {
    uint32_t st = sbase + stage * MSTGB;
    #pragma unroll
    for (int i = 0; i < 2; i++) {
      int u = tid + i*256;
      int row = u >> 2, c = u & 3;
      cp16(st + row*80 + c*16, Ahg + (size_t)arow[i] * K + k0 + c*8);
    }
    #pragma unroll
    for (int i = 0; i < 2; i++) {
      int u = tid + i*256;
      int row = u >> 4, c = u & 15;           // 32 k-rows x 256B
      cp16(st + MAREG + row*272 + c*16, Bhg + (size_t)(k0 + row) * N + n0 + c*8);
    }
    cp_commit();
  };

  int wm = wid >> 1, wn = wid & 1;
  uint32_t aoff  = (uint32_t)((wm*32 + (lane & 15))*80 + ((lane >> 4) << 4));
  uint32_t btoff = (uint32_t)((lane & 15)*272 + wn*128 + ((lane >> 4) << 4));

  float acc[2][8][4];
  #pragma unroll
  for (int i = 0; i < 2; i++)
    #pragma unroll
    for (int j = 0; j < 8; j++)
      #pragma unroll
      for (int q = 0; q < 4; q++) acc[i][j][q] = 0.f;

  auto compute = [&](int stage) {
    uint32_t st = sbase + stage * MSTGB;
    uint32_t bb = st + MAREG;
    #pragma unroll
    for (int ks = 0; ks < 2; ks++) {
      uint32_t ah[2][4];
      ldsm4(ah[0], st + aoff + ks*32);
      ldsm4(ah[1], st + aoff + 16*80 + ks*32);
      #pragma unroll
      for (int g = 0; g < 4; g++) {
        uint32_t bh[4];
        ldsm4t(bh, bb + btoff + ks*16*272 + g*32);
        #pragma unroll
        for (int t = 0; t < 2; t++) {
          #pragma unroll
          for (int mt = 0; mt < 2; mt++)
            mma_f16(acc[mt][g*2 + t], ah[mt], bh + t*2);
        }
      }
    }
  };

  int nkt = K / BKE;
  load_chunk(0, 0);
  if (nkt > 1) load_chunk(1, BKE);
  if (nkt > 2) load_chunk(2, 2*BKE);
  for (int kt = 0; kt < nkt; kt++) {
    if (kt + 2 < nkt) cp_wait<2>();
    else if (kt + 1 < nkt) cp_wait<1>();
    else cp_wait<0>();
    __syncthreads();
    if (kt + 3 < nkt) load_chunk((kt + 3) & 3, (kt + 3) * BKE);
    compute(kt & 3);
  }

  #pragma unroll
  for (int mt = 0; mt < 2; mt++) {
    #pragma unroll
    for (int half = 0; half < 2; half++) {
      int rl = wm*32 + mt*16 + (lane >> 2) + half*8;
      int gmi = m0 + rl;
      if (gmi < mcount) {
        int pr = sPair[rl];
        #pragma unroll
        for (int nt = 0; nt < 8; nt++) {
          int col = n0 + wn*64 + nt*8 + (lane & 3)*2;
          float v0 = acc[mt][nt][half*2 + 0];
          float v1 = acc[mt][nt][half*2 + 1];
          if constexpr (MODE == 2) {
            __half2 hv;
            hv.x = __float2half_rn(gelu_f(v0));
            hv.y = __float2half_rn(gelu_f(v1));
            *(__half2*)(Chalf + (size_t)pr * N + col) = hv;
          } else {
            float w = pairw[pr];
            float* cp = Cf + (size_t)(pr >> 1) * N + col;
            atomicAdd(cp + 0, v0 * w);
            atomicAdd(cp + 1, v1 * w);
          }
        }
      }
    }
  }
}

// ============ Tensor-core flash attention (fp16 split-3, fp32 softmax) ============
__global__ __launch_bounds__(256, 2)
void attn_tc(const __half* __restrict__ qkvh, const __half* __restrict__ qkvl,
             __half* __restrict__ oh, __half* __restrict__ ol) {
  extern __shared__ char dynsm[];
  uint32_t sb = smem_u32(dynsm);
  int tid = threadIdx.x, wid = tid >> 5, lane = tid & 31;
  int qt = blockIdx.x, h = blockIdx.y, b = blockIdx.z;
  int qcol = h*HD, kcol = DIM + h*HD, vcol = 2*DIM + h*HD;
  size_t rowbase = (size_t)b * TSEQ;

  auto loadKV = [&](int kt, int buf) {
    uint32_t kb = sb + AT_KV0 + buf * KVBUF;
    #pragma unroll
    for (int i = 0; i < 2; i++) {
      int u = tid + i*256;
      int r = u >> 3, c = u & 7;
      size_t gk = (rowbase + kt*64 + r) * QKVN;
      uint32_t so = r*AT_ROWB + c*16;
      cp16(kb + so,                qkvh + gk + kcol + c*8);
      cp16(kb + 64*AT_ROWB + so,   qkvl + gk + kcol + c*8);
      cp16(kb + 2*64*AT_ROWB + so, qkvh + gk + vcol + c*8);
      cp16(kb + 3*64*AT_ROWB + so, qkvl + gk + vcol + c*8);
    }
    cp_commit();
  };

  #pragma unroll
  for (int i = 0; i < 4; i++) {
    int u = tid + i*256;
    int r = u >> 3, c = u & 7;
    size_t go = (rowbase + qt*128 + r) * QKVN + qcol + c*8;
    uint32_t so = r*AT_ROWB + c*16;
    cp16(sb + so,         qkvh + go);
    cp16(sb + AT_QL + so, qkvl + go);
  }
  loadKV(0, 0);

  uint32_t aoff = (uint32_t)((wid*16 + (lane & 15))*AT_ROWB + (lane >> 4)*16);
  uint32_t kboff = (uint32_t)(((lane & 7) + ((lane >> 4) << 3))*AT_ROWB + ((lane >> 3) & 1)*16);
  uint32_t voff = (uint32_t)((lane & 15)*AT_ROWB + (lane >> 4)*16);

  float O[8][4];
  #pragma unroll
  for (int i = 0; i < 8; i++)
    #pragma unroll
    for (int j = 0; j < 4; j++) O[i][j] = 0.f;
  float m0 = -1e30f, m1 = -1e30f, l0 = 0.f, l1 = 0.f;

  for (int kt = 0; kt < 16; kt++) {
    cp_wait<0>();
    __syncthreads();
    if (kt < 15) loadKV(kt + 1, (kt + 1) & 1);
    uint32_t kvb = sb + AT_KV0 + (kt & 1) * KVBUF;
    uint32_t KH = kvb, KL = kvb + 64*AT_ROWB, VH = kvb + 2*64*AT_ROWB, VL = kvb + 3*64*AT_ROWB;

    float S[8][4];
    #pragma unroll
    for (int i = 0; i < 8; i++)
      #pragma unroll
      for (int j = 0; j < 4; j++) S[i][j] = 0.f;
    #pragma unroll
    for (int kk = 0; kk < 4; kk++) {
      uint32_t kb = kk*32;
      uint32_t ah[4], al[4];
      ldsm4(ah, sb + aoff + kb);
      ldsm4(al, sb + AT_QL + aoff + kb);
      #pragma unroll
      for (int g = 0; g < 4; g++) {
        uint32_t kh[4], kl[4];
        ldsm4(kh, KH + kboff + g*16*AT_ROWB + kb);
        ldsm4(kl, KL + kboff + g*16*AT_ROWB + kb);
        #pragma unroll
        for (int t = 0; t < 2; t++) {
          float* c = S[g*2 + t];
          mma_f16(c, ah, kl + t*2);
          mma_f16(c, al, kh + t*2);
          mma_f16(c, ah, kh + t*2);
        }
      }
    }

    float mx0 = -1e30f, mx1 = -1e30f;
    #pragma unroll
    for (int nt = 0; nt < 8; nt++) {
      mx0 = fmaxf(mx0, fmaxf(S[nt][0], S[nt][1]));
      mx1 = fmaxf(mx1, fmaxf(S[nt][2], S[nt][3]));
    }
    mx0 = fmaxf(mx0, __shfl_xor_sync(0xffffffffu, mx0, 1));
    mx0 = fmaxf(mx0, __shfl_xor_sync(0xffffffffu, mx0, 2));
    mx1 = fmaxf(mx1, __shfl_xor_sync(0xffffffffu, mx1, 1));
    mx1 = fmaxf(mx1, __shfl_xor_sync(0xffffffffu, mx1, 2));
    float mn0 = fmaxf(m0, mx0), mn1 = fmaxf(m1, mx1);
    float a0 = __expf(m0 - mn0), a1 = __expf(m1 - mn1);
    float s0 = 0.f, s1 = 0.f;
    #pragma unroll
    for (int nt = 0; nt < 8; nt++) {
      S[nt][0] = __expf(S[nt][0] - mn0);
      S[nt][1] = __expf(S[nt][1] - mn0);
      S[nt][2] = __expf(S[nt][2] - mn1);
      S[nt][3] = __expf(S[nt][3] - mn1);
      s0 += S[nt][0] + S[nt][1];
      s1 += S[nt][2] + S[nt][3];
    }
    s0 += __shfl_xor_sync(0xffffffffu, s0, 1);
    s0 += __shfl_xor_sync(0xffffffffu, s0, 2);
    s1 += __shfl_xor_sync(0xffffffffu, s1, 1);
    s1 += __shfl_xor_sync(0xffffffffu, s1, 2);
    l0 = l0*a0 + s0; l1 = l1*a1 + s1;
    m0 = mn0; m1 = mn1;
    #pragma unroll
    for (int nt = 0; nt < 8; nt++) {
      O[nt][0] *= a0; O[nt][1] *= a0;
      O[nt][2] *= a1; O[nt][3] *= a1;
    }

    #pragma unroll
    for (int kk = 0; kk < 4; kk++) {
      uint32_t ph[4], pl[4];
      #pragma unroll
      for (int half = 0; half < 2; half++) {
        float* sp = S[kk*2 + half];
        float h00 = __half2float(__float2half_rn(sp[0]));
        float h01 = __half2float(__float2half_rn(sp[1]));
        float h02 = __half2float(__float2half_rn(sp[2]));
        float h03 = __half2float(__float2half_rn(sp[3]));
        ph[half*2 + 0] = packh2(h00, h01);
        ph[half*2 + 1] = packh2(h02, h03);
        pl[half*2 + 0] = packh2(sp[0] - h00, sp[1] - h01);
        pl[half*2 + 1] = packh2(sp[2] - h02, sp[3] - h03);
      }
      #pragma unroll
      for (int nb = 0; nb < 4; nb++) {
        uint32_t vh[4], vl[4];
        uint32_t va = voff + kk*16*AT_ROWB + nb*32;
        ldsm4t(vh, VH + va);
        ldsm4t(vl, VL + va);
        #pragma unroll
        for (int t = 0; t < 2; t++) {
          float* c = O[nb*2 + t];
          mma_f16(c, ph, vl + t*2);
          mma_f16(c, pl, vh + t*2);
          mma_f16(c, ph, vh + t*2);
        }
      }
    }
  }

  float inv0 = 1.0f / l0, inv1 = 1.0f / l1;
  int r0 = qt*128 + wid*16 + (lane >> 2);
  size_t ob0 = (rowbase + r0) * DIM;
  size_t ob1 = (rowbase + r0 + 8) * DIM;
  #pragma unroll
  for (int nt = 0; nt < 8; nt++) {
    int col = h*HD + nt*8 + (lane & 3)*2;
    float v0 = O[nt][0]*inv0, v1 = O[nt][1]*inv0;
    float v2 = O[nt][2]*inv1, v3 = O[nt][3]*inv1;
    float h0 = __half2float(__float2half_rn(v0)), h1 = __half2float(__float2half_rn(v1));
    float h2 = __half2float(__float2half_rn(v2)), h3 = __half2float(__float2half_rn(v3));
    *(uint32_t*)(oh + ob0 + col) = packh2(v0, v1);
    *(uint32_t*)(ol + ob0 + col) = packh2(v0 - h0, v1 - h1);
    *(uint32_t*)(oh + ob1 + col) = packh2(v2, v3);
    *(uint32_t*)(ol + ob1 + col) = packh2(v2 - h2, v3 - h3);
  }
}

// --------- transpose + fp16 split (QKV/proj weights only) ---------
__global__ void transpose_split(const float* __restrict__ in, __half* __restrict__ oh,
                                __half* __restrict__ ol, int R, int C) {
  __shared__ float t[32][33];
  size_t eo = (size_t)blockIdx.z * R * C;
  int c0 = blockIdx.x * 32, r0 = blockIdx.y * 32;
  int tx = threadIdx.x, ty = threadIdx.y;
  #pragma unroll
  for (int i = 0; i < 32; i += 8)
    t[ty + i][tx] = in[eo + (size_t)(r0 + ty + i) * C + c0 + tx];
  __syncthreads();
  int txl = tx & 15, txh = tx >> 4;
  #pragma unroll
  for (int i = 0; i < 32; i += 16) {
    int orow = ty*2 + txh + i;
    float v0 = t[2*txl][orow], v1 = t[2*txl + 1][orow];
    size_t o = eo + (size_t)(c0 + orow) * R + r0 + 2*txl;
    __half h0 = __float2half_rn(v0), h1 = __float2half_rn(v1);
    __half2 hv; hv.x = h0; hv.y = h1;
    *(__half2*)(oh + o) = hv;
    __half2 lv;
    lv.x = __float2half_rn(v0 - __half2float(h0));
    lv.y = __float2half_rn(v1 - __half2float(h1));
    *(__half2*)(ol + o) = lv;
  }
}

// --------- elementwise f32 -> fp16 convert (MoE weights, native layout) ---------
__global__ void convert_h(const float* __restrict__ in, __half* __restrict__ out, int n) {
  int i = (blockIdx.x * 256 + threadIdx.x) * 8;
  if (i >= n) return;
  float4 a = *(const float4*)(in + i);
  float4 b = *(const float4*)(in + i + 4);
  uint4 o;
  o.x = packh2(a.x, a.y);
  o.y = packh2(a.z, a.w);
  o.z = packh2(b.x, b.y);
  o.w = packh2(b.z, b.w);
  *(uint4*)(out + i) = o;
}

// ---------------- LayerNorm (f32 opt + fp16 hi (+lo) + optional raw copy) ----------------
__global__ void ln_kernel(const float* __restrict__ in, const float* __restrict__ gam,
                          const float* __restrict__ bet, float* __restrict__ of,
                          __half* __restrict__ oh, __half* __restrict__ ol,
                          float* __restrict__ ocopy) {
  __shared__ float red[256];
  int row = blockIdx.x, tid = threadIdx.x;
  const float* x = in + (size_t)row * DIM;
  float v0 = x[tid], v1 = x[tid+256], v2 = x[tid+512];
  red[tid] = v0+v1+v2; __syncthreads();
  for (int o=128;o;o>>=1){ if (tid<o) red[tid]+=red[tid+o]; __syncthreads(); }
  float mean = red[0] * (1.0f/DIM);
  __syncthreads();
  float d0=v0-mean, d1=v1-mean, d2=v2-mean;
  red[tid] = d0*d0+d1*d1+d2*d2; __syncthreads();
  for (int o=128;o;o>>=1){ if (tid<o) red[tid]+=red[tid+o]; __syncthreads(); }
  float r = rsqrtf(red[0]*(1.0f/DIM) + 1e-5f);
  size_t base = (size_t)row * DIM;
  #pragma unroll
  for (int j = 0; j < 3; j++) {
    int c = tid + j*256;
    float raw = (j==0) ? v0 : (j==1) ? v1 : v2;
    float d = (j==0) ? d0 : (j==1) ? d1 : d2;
    float v = d*r*gam[c] + bet[c];
    if (of) of[base + c] = v;
    if (ocopy) ocopy[base + c] = raw;
    __half h = __float2half_rn(v);
    oh[base + c] = h;
    if (ol) ol[base + c] = __float2half_rn(v - __half2float(h));
  }
}

// ---------------- Router ----------------
__global__ void zero_counts(int* c){ if (threadIdx.x < NE) c[threadIdx.x]=0; }

__global__ void router_kernel(const float* __restrict__ xln2, const float* __restrict__ Wr,
                              int* __restrict__ bucket, float* __restrict__ pairw,
                              int* __restrict__ count) {
  int gw = (int)((blockIdx.x * blockDim.x + threadIdx.x) >> 5);
  int lane = threadIdx.x & 31;
  if (gw >= NTOK) return;
  const float* x = xln2 + (size_t)gw * DIM;
  float lg[NE];
  #pragma unroll
  for (int e=0;e<NE;e++) lg[e]=0.f;
  for (int d=lane; d<DIM; d+=32) {
    float xv = x[d];
    #pragma unroll
    for (int e=0;e<NE;e++) lg[e] += xv * Wr[d*NE + e];
  }
  #pragma unroll
  for (int e=0;e<NE;e++)
    for (int off=16; off; off>>=1) lg[e] += __shfl_xor_sync(0xffffffffu, lg[e], off);
  if (lane == 0) {
    int i0 = 0;
    #pragma unroll
    for (int e=1;e<NE;e++) if (lg[e] > lg[i0]) i0 = e;
    int i1 = (i0==0) ? 1 : 0;
    #pragma unroll
    for (int e=0;e<NE;e++) { if (e==i0) continue; if (lg[e] > lg[i1]) i1 = e; }
    float w0 = 1.f / (1.f + expf(lg[i1] - lg[i0]));
    float w1 = 1.f - w0;
    int p0 = gw*2, p1 = gw*2+1;
    pairw[p0] = w0; pairw[p1] = w1;
    int q0 = atomicAdd(&count[i0], 1); bucket[i0*NPAIR + q0] = p0;
    int q1 = atomicAdd(&count[i1], 1); bucket[i1*NPAIR + q1] = p1;
  }
}

extern "C" void kernel_launch(void* const* d_in, const int* in_sizes, int n_in,
                              void* d_out, int out_size) {
  const float* x       = (const float*)d_in[0];
  const float* Wqkv    = (const float*)d_in[1];
  const float* Wproj   = (const float*)d_in[2];
  const float* Wrouter = (const float*)d_in[3];
  const float* W1      = (const float*)d_in[4];
  const float* W2      = (const float*)d_in[5];
  const float* ln1g    = (const float*)d_in[6];
  const float* ln1b    = (const float*)d_in[7];
  const float* ln2g    = (const float*)d_in[8];
  const float* ln2b    = (const float*)d_in[9];
  float* out = (float*)d_out;

  Scratch* s = nullptr;
  cudaGetSymbolAddress((void**)&s, g_s);

  cudaFuncSetAttribute(attn_tc, cudaFuncAttributeMaxDynamicSharedMemorySize, AT_SMEM);
  cudaFuncSetAttribute(gemm_split<0>, cudaFuncAttributeMaxDynamicSharedMemorySize, GSMEM_SPLIT);
  cudaFuncSetAttribute(gemm_split<1>, cudaFuncAttributeMaxDynamicSharedMemorySize, GSMEM_SPLIT);
  cudaFuncSetAttribute(gemm_moe<2>, cudaFuncAttributeMaxDynamicSharedMemorySize, GSMEM_MOE);
  cudaFuncSetAttribute(gemm_moe<3>, cudaFuncAttributeMaxDynamicSharedMemorySize, GSMEM_MOE);

  dim3 tb(32, 8);
  transpose_split<<<dim3(QKVN/32, DIM/32, 1), tb>>>(Wqkv, s->Wqkvth, s->Wqkvtl, DIM, QKVN);
  transpose_split<<<dim3(DIM/32, DIM/32, 1), tb>>>(Wproj, s->Wprojth, s->Wprojtl, DIM, DIM);
  convert_h<<<(NE*DIM*FFD)/2048, 256>>>(W1, s->W1h, NE*DIM*FFD);
  convert_h<<<(NE*FFD*DIM)/2048, 256>>>(W2, s->W2h, NE*FFD*DIM);

  // x -> ln1 -> qkv(fp16 hi/lo, Q scaled) -> attention(TC) -> proj+residual -> x1
  ln_kernel<<<NTOK, 256>>>(x, ln1g, ln1b, nullptr, s->xln1h, s->xln1l, nullptr);
  gemm_split<0><<<dim3(QKVN/128, NTOK/128, 1), 256, GSMEM_SPLIT>>>(
      s->xln1h, s->xln1l, s->Wqkvth, s->Wqkvtl, nullptr, s->qkvh, s->qkvl,
      NTOK, QKVN, DIM, nullptr);
  attn_tc<<<dim3(TSEQ/128, NH, NB), 256, AT_SMEM>>>(s->qkvh, s->qkvl, s->attnh, s->attnl);
  gemm_split<1><<<dim3(DIM/128, NTOK/128, 1), 256, GSMEM_SPLIT>>>(
      s->attnh, s->attnl, s->Wprojth, s->Wprojtl, s->x1, nullptr, nullptr,
      NTOK, DIM, DIM, x);

  // x1 -> ln2 (copies x1 into out) -> router -> MoE (down accumulates into out)
  ln_kernel<<<NTOK, 256>>>(s->x1, ln2g, ln2b, s->xln2, s->xln2h, nullptr, out);
  zero_counts<<<1, 32>>>(s->count);
  router_kernel<<<NTOK/8, 256>>>(s->xln2, Wrouter, s->bucket, s->pairw, s->count);
  gemm_moe<2><<<dim3(FFD/128, NPAIR/128, NE), 256, GSMEM_MOE>>>(
      s->xln2h, s->W1h, nullptr, s->Hh, FFD, DIM, s->bucket, s->count, nullptr);
  gemm_moe<3><<<dim3(DIM/128, NPAIR/128, NE), 256, GSMEM_MOE>>>(
      s->Hh, s->W2h, out, nullptr, DIM, FFD, s->bucket, s->count, s->pairw);
}

// round 11
// speedup vs baseline: 3.6904x; 1.0415x over previous
#include <cuda_runtime.h>
#include <cuda_fp16.h>
#include <math.h>
#include <stdint.h>

#define NTOK 4096
#define DIM 768
#define QKVN (3*DIM)
#define FFD 3072
#define NE 8
#define NPAIR (NTOK*2)
#define TSEQ 1024
#define NB 4
#define NH 12
#define HD 64

// split GEMM: swizzled 64B rows, 3 stages x (Ah,Al,Bh,Bl), BK=32
#define SBKE 32
#define SAREG 8192
#define SSTGB (4*SAREG)
#define GSMEM_SPLIT (3*SSTGB)           // 98304

// MoE GEMM: BK=64. A 128x144B + B-trans 64x272B, 3 stages
#define MBKE 64
#define MAREG (128*144)                 // 18432
#define MBREG (64*272)                  // 17408
#define MSTGB (MAREG + MBREG)           // 35840
#define GSMEM_MOE (3*MSTGB)             // 107520

// attention: Q 128x64 hi/lo + double-buffered KV
#define AT_ROWB 144
#define AT_QL   (128*AT_ROWB)
#define AT_KV0  (2*128*AT_ROWB)
#define KVBUF   (4*64*AT_ROWB)
#define AT_SMEM (AT_KV0 + 2*KVBUF)      // 110592

struct Scratch {
  float x1[(size_t)NTOK*DIM];
  __half qkvh[(size_t)NTOK*QKVN], qkvl[(size_t)NTOK*QKVN];
  __half xln1h[(size_t)NTOK*DIM], xln1l[(size_t)NTOK*DIM];
  __half attnh[(size_t)NTOK*DIM], attnl[(size_t)NTOK*DIM];
  __half xln2h[(size_t)NTOK*DIM];
  __half Hh[(size_t)NPAIR*FFD];
  __half Wqkvth[(size_t)QKVN*DIM], Wqkvtl[(size_t)QKVN*DIM];
  __half Wprojth[(size_t)DIM*DIM], Wprojtl[(size_t)DIM*DIM];
  __half W1h[(size_t)NE*DIM*FFD];       // native [e][k][n]
  __half W2h[(size_t)NE*FFD*DIM];       // native [e][k][n]
  float pairw[NPAIR];
  int bucket[NE*NPAIR];
  int count[NE];
};
__device__ Scratch g_s;

__device__ __forceinline__ float gelu_f(float v) {
  return 0.5f * v * (1.0f + erff(v * 0.70710678118654752f));
}
__device__ __forceinline__ uint32_t smem_u32(const void* p) {
  uint32_t a;
  asm("{ .reg .u64 t; cvta.to.shared.u64 t, %1; cvt.u32.u64 %0, t; }" : "=r"(a) : "l"(p));
  return a;
}
__device__ __forceinline__ void cp16(uint32_t dst, const void* src) {
  asm volatile("cp.async.cg.shared.global [%0], [%1], 16;\n" :: "r"(dst), "l"(src));
}
__device__ __forceinline__ void cp_commit() { asm volatile("cp.async.commit_group;\n"); }
template<int N> __device__ __forceinline__ void cp_wait() {
  asm volatile("cp.async.wait_group %0;\n" :: "n"(N));
}
__device__ __forceinline__ void ldsm4(uint32_t* r, uint32_t addr) {
  asm volatile("ldmatrix.sync.aligned.m8n8.x4.shared.b16 {%0,%1,%2,%3}, [%4];"
    : "=r"(r[0]), "=r"(r[1]), "=r"(r[2]), "=r"(r[3]) : "r"(addr));
}
__device__ __forceinline__ void ldsm4t(uint32_t* r, uint32_t addr) {
  asm volatile("ldmatrix.sync.aligned.m8n8.x4.trans.shared.b16 {%0,%1,%2,%3}, [%4];"
    : "=r"(r[0]), "=r"(r[1]), "=r"(r[2]), "=r"(r[3]) : "r"(addr));
}
__device__ __forceinline__ void mma_f16(float* c, const uint32_t* a, const uint32_t* b) {
  asm volatile(
    "mma.sync.aligned.m16n8k16.row.col.f32.f16.f16.f32 "
    "{%0,%1,%2,%3},{%4,%5,%6,%7},{%8,%9},{%0,%1,%2,%3};\n"
    : "+f"(c[0]), "+f"(c[1]), "+f"(c[2]), "+f"(c[3])
    : "r"(a[0]), "r"(a[1]), "r"(a[2]), "r"(a[3]), "r"(b[0]), "r"(b[1]));
}
__device__ __forceinline__ uint32_t packh2(float x, float y) {
  __half2 h; h.x = __float2half_rn(x); h.y = __float2half_rn(y);
  return *(uint32_t*)&h;
}
__device__ __forceinline__ uint32_t swz(int row, int c) {
  return (uint32_t)(row*64 + ((c ^ ((row >> 1) & 3)) << 4));
}

// =============== split-3 fp16 GEMM (router-safe path), swizzled, 3-stage ===============
// MODE 0: qkv = A@B -> fp16 hi/lo (Q scaled 0.125)   MODE 1: x1 = A@B + resid -> f32
template<int MODE>
__global__ __launch_bounds__(256, 2)
void gemm_split(const __half* __restrict__ Ahg, const __half* __restrict__ Alg,
                const __half* __restrict__ Bhg, const __half* __restrict__ Blg,
                float* __restrict__ Cf, __half* __restrict__ Chalf, __half* __restrict__ Chalf2,
                int M, int N, int K, const float* __restrict__ resid)
{
  extern __shared__ char dynsm[];
  int tid = threadIdx.x, wid = tid >> 5, lane = tid & 31;
  int m0 = blockIdx.y * 128;
  int n0 = blockIdx.x * 128;
  uint32_t sbase = smem_u32(dynsm);

  auto load_chunk = [&](int stage, int k0) {
    uint32_t st = sbase + stage * SSTGB;
    #pragma unroll
    for (int i = 0; i < 2; i++) {
      int u = tid + i*256;
      int row = u >> 2, c = u & 3;
      uint32_t so = swz(row, c);
      size_t go = (size_t)(m0 + row) * K + k0 + c*8;
      cp16(st + so,         Ahg + go);
      cp16(st + SAREG + so, Alg + go);
    }
    #pragma unroll
    for (int i = 0; i < 2; i++) {
      int u = tid + i*256;
      int row = u >> 2, c = u & 3;
      uint32_t so = swz(row, c);
      size_t go = (size_t)(n0 + row) * K + k0 + c*8;
      cp16(st + 2*SAREG + so, Bhg + go);
      cp16(st + 3*SAREG + so, Blg + go);
    }
    cp_commit();
  };

  int wm = wid >> 1, wn = wid & 1;
  int arow = wm*32 + (lane & 15);
  int acs  = (lane >> 4);
  int brow = wn*64 + (lane & 7) + ((lane >> 4) << 3);
  int bcs  = (lane >> 3) & 1;

  float acc[2][8][4];
  #pragma unroll
  for (int i = 0; i < 2; i++)
    #pragma unroll
    for (int j = 0; j < 8; j++)
      #pragma unroll
      for (int q = 0; q < 4; q++) acc[i][j][q] = 0.f;

  auto compute = [&](int stage) {
    uint32_t st = sbase + stage * SSTGB;
    #pragma unroll
    for (int ks = 0; ks < 2; ks++) {
      uint32_t ah[2][4], al[2][4];
      ldsm4(ah[0], st +         swz(arow,      acs + ks*2));
      ldsm4(ah[1], st +         swz(arow + 16, acs + ks*2));
      ldsm4(al[0], st + SAREG + swz(arow,      acs + ks*2));
      ldsm4(al[1], st + SAREG + swz(arow + 16, acs + ks*2));
      #pragma unroll
      for (int g = 0; g < 4; g++) {
        uint32_t bh[4], bl[4];
        ldsm4(bh, st + 2*SAREG + swz(brow + g*16, bcs + ks*2));
        ldsm4(bl, st + 3*SAREG + swz(brow + g*16, bcs + ks*2));
        #pragma unroll
        for (int t = 0; t < 2; t++) {
          #pragma unroll
          for (int mt = 0; mt < 2; mt++) {
            float* c = acc[mt][g*2 + t];
            mma_f16(c, ah[mt], bl + t*2);
            mma_f16(c, al[mt], bh + t*2);
            mma_f16(c, ah[mt], bh + t*2);
          }
        }
      }
    }
  };

  int nkt = K / SBKE;
  load_chunk(0, 0);
  if (nkt > 1) load_chunk(1, SBKE);
  for (int kt = 0; kt < nkt; kt++) {
    if (kt + 1 < nkt) cp_wait<1>(); else cp_wait<0>();
    __syncthreads();
    if (kt + 2 < nkt) load_chunk((kt + 2) % 3, (kt + 2) * SBKE);
    compute(kt % 3);
  }

  #pragma unroll
  for (int mt = 0; mt < 2; mt++) {
    #pragma unroll
    for (int half = 0; half < 2; half++) {
      int gmi = m0 + wm*32 + mt*16 + (lane >> 2) + half*8;
      #pragma unroll
      for (int nt = 0; nt < 8; nt++) {
        int col = n0 + wn*64 + nt*8 + (lane & 3)*2;
        float v0 = acc[mt][nt][half*2 + 0];
        float v1 = acc[mt][nt][half*2 + 1];
        if constexpr (MODE == 0) {
          float sc = (col < DIM) ? 0.125f : 1.0f;
          v0 *= sc; v1 *= sc;
          __half h0 = __float2half_rn(v0), h1 = __float2half_rn(v1);
          __half2 hv; hv.x = h0; hv.y = h1;
          __half2 lv;
          lv.x = __float2half_rn(v0 - __half2float(h0));
          lv.y = __float2half_rn(v1 - __half2float(h1));
          *(__half2*)(Chalf + (size_t)gmi * N + col) = hv;
          *(__half2*)(Chalf2 + (size_t)gmi * N + col) = lv;
        } else {
          const float* rp = resid + (size_t)gmi * N + col;
          *(float2*)(Cf + (size_t)gmi * N + col) = make_float2(v0 + rp[0], v1 + rp[1]);
        }
      }
    }
  }
}

// =============== MoE fp16 GEMM: BK=64, native [k][n] weights via ldsm4t, 3-stage ===============
// MODE 2: H[pair] = gelu(A[tok]@W1[e]) -> fp16    MODE 3: out[tok] += w*(H[pair]@W2[e])
template<int MODE>
__global__ __launch_bounds__(256, 2)
void gemm_moe(const __half* __restrict__ Ahg, const __half* __restrict__ Bhg,
              float* __restrict__ Cf, __half* __restrict__ Chalf,
              int N, int K,
              const int* __restrict__ bucket, const int* __restrict__ counts,
              const float* __restrict__ pairw)
{
  extern __shared__ char dynsm[];
  __shared__ int sPair[128];
  int tid = threadIdx.x, wid = tid >> 5, lane = tid & 31;
  int e = blockIdx.z;
  int mcount = counts[e];
  int m0 = blockIdx.y * 128;
  if (m0 >= mcount) return;
  int n0 = blockIdx.x * 128;
  Bhg += (size_t)e * K * N;
  if (tid < 128) {
    int gm = m0 + tid;
    sPair[tid] = bucket[e * NPAIR + (gm < mcount ? gm : mcount - 1)];
  }
  __syncthreads();

  uint32_t sbase = smem_u32(dynsm);

  int arow4[4];
  #pragma unroll
  for (int i = 0; i < 4; i++) {
    int row = (tid + i*256) >> 3;
    arow4[i] = (MODE == 2) ? (sPair[row] >> 1) : sPair[row];
  }

  auto load_chunk = [&](int stage, int k0) {
    uint32_t st = sbase + stage * MSTGB;
    #pragma unroll
    for (int i = 0; i < 4; i++) {
      int u = tid + i*256;
      int row = u >> 3, c = u & 7;
      cp16(st + row*144 + c*16, Ahg + (size_t)arow4[i] * K + k0 + c*8);
    }
    #pragma unroll
    for (int i = 0; i < 4; i++) {
      int u = tid + i*256;
      int row = u >> 4, c = u & 15;          // 64 k-rows x 256B
      cp16(st + MAREG + row*272 + c*16, Bhg + (size_t)(k0 + row) * N + n0 + c*8);
    }
    cp_commit();
  };

  int wm = wid >> 1, wn = wid & 1;
  uint32_t aoff  = (uint32_t)((wm*32 + (lane & 15))*144 + ((lane >> 4) << 4));
  uint32_t btoff = (uint32_t)((lane & 15)*272 + wn*128 + ((lane >> 4) << 4));

  float acc[2][8][4];
  #pragma unroll
  for (int i = 0; i < 2; i++)
    #pragma unroll
    for (int j = 0; j < 8; j++)
      #pragma unroll
      for (int q = 0; q < 4; q++) acc[i][j][q] = 0.f;

  auto compute = [&](int stage) {
    uint32_t st = sbase + stage * MSTGB;
    uint32_t bb = st + MAREG;
    #pragma unroll
    for (int ks = 0; ks < 4; ks++) {
      uint32_t ah[2][4];
      ldsm4(ah[0], st + aoff + ks*32);
      ldsm4(ah[1], st + aoff + 16*144 + ks*32);
      #pragma unroll
      for (int g = 0; g < 4; g++) {
        uint32_t bh[4];
        ldsm4t(bh, bb + btoff + ks*16*272 + g*32);
        #pragma unroll
        for (int t = 0; t < 2; t++) {
          #pragma unroll
          for (int mt = 0; mt < 2; mt++)
            mma_f16(acc[mt][g*2 + t], ah[mt], bh + t*2);
        }
      }
    }
  };

  int nkt = K / MBKE;
  load_chunk(0, 0);
  if (nkt > 1) load_chunk(1, MBKE);
  for (int kt = 0; kt < nkt; kt++) {
    if (kt + 1 < nkt) cp_wait<1>(); else cp_wait<0>();
    __syncthreads();
    if (kt + 2 < nkt) load_chunk((kt + 2) % 3, (kt + 2) * MBKE);
    compute(kt % 3);
  }

  #pragma unroll
  for (int mt = 0; mt < 2; mt++) {
    #pragma unroll
    for (int half = 0; half < 2; half++) {
      int rl = wm*32 + mt*16 + (lane >> 2) + half*8;
      int gmi = m0 + rl;
      if (gmi < mcount) {
        int pr = sPair[rl];
        #pragma unroll
        for (int nt = 0; nt < 8; nt++) {
          int col = n0 + wn*64 + nt*8 + (lane & 3)*2;
          float v0 = acc[mt][nt][half*2 + 0];
          float v1 = acc[mt][nt][half*2 + 1];
          if constexpr (MODE == 2) {
            __half2 hv;
            hv.x = __float2half_rn(gelu_f(v0));
            hv.y = __float2half_rn(gelu_f(v1));
            *(__half2*)(Chalf + (size_t)pr * N + col) = hv;
          } else {
            float w = pairw[pr];
            float* cp = Cf + (size_t)(pr >> 1) * N + col;
            atomicAdd(cp + 0, v0 * w);
            atomicAdd(cp + 1, v1 * w);
          }
        }
      }
    }
  }
}

// ============ Tensor-core flash attention (fp16 split-3, fp32 softmax) ============
__global__ __launch_bounds__(256, 2)
void attn_tc(const __half* __restrict__ qkvh, const __half* __restrict__ qkvl,
             __half* __restrict__ oh, __half* __restrict__ ol) {
  extern __shared__ char dynsm[];
  uint32_t sb = smem_u32(dynsm);
  int tid = threadIdx.x, wid = tid >> 5, lane = tid & 31;
  int qt = blockIdx.x, h = blockIdx.y, b = blockIdx.z;
  int qcol = h*HD, kcol = DIM + h*HD, vcol = 2*DIM + h*HD;
  size_t rowbase = (size_t)b * TSEQ;

  auto loadKV = [&](int kt, int buf) {
    uint32_t kb = sb + AT_KV0 + buf * KVBUF;
    #pragma unroll
    for (int i = 0; i < 2; i++) {
      int u = tid + i*256;
      int r = u >> 3, c = u & 7;
      size_t gk = (rowbase + kt*64 + r) * QKVN;
      uint32_t so = r*AT_ROWB + c*16;
      cp16(kb + so,                qkvh + gk + kcol + c*8);
      cp16(kb + 64*AT_ROWB + so,   qkvl + gk + kcol + c*8);
      cp16(kb + 2*64*AT_ROWB + so, qkvh + gk + vcol + c*8);
      cp16(kb + 3*64*AT_ROWB + so, qkvl + gk + vcol + c*8);
    }
    cp_commit();
  };

  #pragma unroll
  for (int i = 0; i < 4; i++) {
    int u = tid + i*256;
    int r = u >> 3, c = u & 7;
    size_t go = (rowbase + qt*128 + r) * QKVN + qcol + c*8;
    uint32_t so = r*AT_ROWB + c*16;
    cp16(sb + so,         qkvh + go);
    cp16(sb + AT_QL + so, qkvl + go);
  }
  loadKV(0, 0);

  uint32_t aoff = (uint32_t)((wid*16 + (lane & 15))*AT_ROWB + (lane >> 4)*16);
  uint32_t kboff = (uint32_t)(((lane & 7) + ((lane >> 4) << 3))*AT_ROWB + ((lane >> 3) & 1)*16);
  uint32_t voff = (uint32_t)((lane & 15)*AT_ROWB + (lane >> 4)*16);

  float O[8][4];
  #pragma unroll
  for (int i = 0; i < 8; i++)
    #pragma unroll
    for (int j = 0; j < 4; j++) O[i][j] = 0.f;
  float m0 = -1e30f, m1 = -1e30f, l0 = 0.f, l1 = 0.f;

  for (int kt = 0; kt < 16; kt++) {
    cp_wait<0>();
    __syncthreads();
    if (kt < 15) loadKV(kt + 1, (kt + 1) & 1);
    uint32_t kvb = sb + AT_KV0 + (kt & 1) * KVBUF;
    uint32_t KH = kvb, KL = kvb + 64*AT_ROWB, VH = kvb + 2*64*AT_ROWB, VL = kvb + 3*64*AT_ROWB;

    float S[8][4];
    #pragma unroll
    for (int i = 0; i < 8; i++)
      #pragma unroll
      for (int j = 0; j < 4; j++) S[i][j] = 0.f;
    #pragma unroll
    for (int kk = 0; kk < 4; kk++) {
      uint32_t kb = kk*32;
      uint32_t ah[4], al[4];
      ldsm4(ah, sb + aoff + kb);
      ldsm4(al, sb + AT_QL + aoff + kb);
      #pragma unroll
      for (int g = 0; g < 4; g++) {
        uint32_t kh[4], kl[4];
        ldsm4(kh, KH + kboff + g*16*AT_ROWB + kb);
        ldsm4(kl, KL + kboff + g*16*AT_ROWB + kb);
        #pragma unroll
        for (int t = 0; t < 2; t++) {
          float* c = S[g*2 + t];
          mma_f16(c, ah, kl + t*2);
          mma_f16(c, al, kh + t*2);
          mma_f16(c, ah, kh + t*2);
        }
      }
    }

    float mx0 = -1e30f, mx1 = -1e30f;
    #pragma unroll
    for (int nt = 0; nt < 8; nt++) {
      mx0 = fmaxf(mx0, fmaxf(S[nt][0], S[nt][1]));
      mx1 = fmaxf(mx1, fmaxf(S[nt][2], S[nt][3]));
    }
    mx0 = fmaxf(mx0, __shfl_xor_sync(0xffffffffu, mx0, 1));
    mx0 = fmaxf(mx0, __shfl_xor_sync(0xffffffffu, mx0, 2));
    mx1 = fmaxf(mx1, __shfl_xor_sync(0xffffffffu, mx1, 1));
    mx1 = fmaxf(mx1, __shfl_xor_sync(0xffffffffu, mx1, 2));
    float mn0 = fmaxf(m0, mx0), mn1 = fmaxf(m1, mx1);
    float a0 = __expf(m0 - mn0), a1 = __expf(m1 - mn1);
    float s0 = 0.f, s1 = 0.f;
    #pragma unroll
    for (int nt = 0; nt < 8; nt++) {
      S[nt][0] = __expf(S[nt][0] - mn0);
      S[nt][1] = __expf(S[nt][1] - mn0);
      S[nt][2] = __expf(S[nt][2] - mn1);
      S[nt][3] = __expf(S[nt][3] - mn1);
      s0 += S[nt][0] + S[nt][1];
      s1 += S[nt][2] + S[nt][3];
    }
    s0 += __shfl_xor_sync(0xffffffffu, s0, 1);
    s0 += __shfl_xor_sync(0xffffffffu, s0, 2);
    s1 += __shfl_xor_sync(0xffffffffu, s1, 1);
    s1 += __shfl_xor_sync(0xffffffffu, s1, 2);
    l0 = l0*a0 + s0; l1 = l1*a1 + s1;
    m0 = mn0; m1 = mn1;
    #pragma unroll
    for (int nt = 0; nt < 8; nt++) {
      O[nt][0] *= a0; O[nt][1] *= a0;
      O[nt][2] *= a1; O[nt][3] *= a1;
    }

    #pragma unroll
    for (int kk = 0; kk < 4; kk++) {
      uint32_t ph[4], pl[4];
      #pragma unroll
      for (int half = 0; half < 2; half++) {
        float* sp = S[kk*2 + half];
        float h00 = __half2float(__float2half_rn(sp[0]));
        float h01 = __half2float(__float2half_rn(sp[1]));
        float h02 = __half2float(__float2half_rn(sp[2]));
        float h03 = __half2float(__float2half_rn(sp[3]));
        ph[half*2 + 0] = packh2(h00, h01);
        ph[half*2 + 1] = packh2(h02, h03);
        pl[half*2 + 0] = packh2(sp[0] - h00, sp[1] - h01);
        pl[half*2 + 1] = packh2(sp[2] - h02, sp[3] - h03);
      }
      #pragma unroll
      for (int nb = 0; nb < 4; nb++) {
        uint32_t vh[4], vl[4];
        uint32_t va = voff + kk*16*AT_ROWB + nb*32;
        ldsm4t(vh, VH + va);
        ldsm4t(vl, VL + va);
        #pragma unroll
        for (int t = 0; t < 2; t++) {
          float* c = O[nb*2 + t];
          mma_f16(c, ph, vl + t*2);
          mma_f16(c, pl, vh + t*2);
          mma_f16(c, ph, vh + t*2);
        }
      }
    }
  }

  float inv0 = 1.0f / l0, inv1 = 1.0f / l1;
  int r0 = qt*128 + wid*16 + (lane >> 2);
  size_t ob0 = (rowbase + r0) * DIM;
  size_t ob1 = (rowbase + r0 + 8) * DIM;
  #pragma unroll
  for (int nt = 0; nt < 8; nt++) {
    int col = h*HD + nt*8 + (lane & 3)*2;
    float v0 = O[nt][0]*inv0, v1 = O[nt][1]*inv0;
    float v2 = O[nt][2]*inv1, v3 = O[nt][3]*inv1;
    float h0 = __half2float(__float2half_rn(v0)), h1 = __half2float(__float2half_rn(v1));
    float h2 = __half2float(__float2half_rn(v2)), h3 = __half2float(__float2half_rn(v3));
    *(uint32_t*)(oh + ob0 + col) = packh2(v0, v1);
    *(uint32_t*)(ol + ob0 + col) = packh2(v0 - h0, v1 - h1);
    *(uint32_t*)(oh + ob1 + col) = packh2(v2, v3);
    *(uint32_t*)(ol + ob1 + col) = packh2(v2 - h2, v3 - h3);
  }
}

// --------- transpose + fp16 split (QKV/proj weights only) ---------
__global__ void transpose_split(const float* __restrict__ in, __half* __restrict__ oh,
                                __half* __restrict__ ol, int R, int C) {
  __shared__ float t[32][33];
  size_t eo = (size_t)blockIdx.z * R * C;
  int c0 = blockIdx.x * 32, r0 = blockIdx.y * 32;
  int tx = threadIdx.x, ty = threadIdx.y;
  #pragma unroll
  for (int i = 0; i < 32; i += 8)
    t[ty + i][tx] = in[eo + (size_t)(r0 + ty + i) * C + c0 + tx];
  __syncthreads();
  int txl = tx & 15, txh = tx >> 4;
  #pragma unroll
  for (int i = 0; i < 32; i += 16) {
    int orow = ty*2 + txh + i;
    float v0 = t[2*txl][orow], v1 = t[2*txl + 1][orow];
    size_t o = eo + (size_t)(c0 + orow) * R + r0 + 2*txl;
    *(__half2*)(oh + o) = *(__half2*)&(uint32_t&)*(uint32_t[]){packh2(v0, v1)};
    __half h0 = __float2half_rn(v0), h1 = __float2half_rn(v1);
    __half2 lv;
    lv.x = __float2half_rn(v0 - __half2float(h0));
    lv.y = __float2half_rn(v1 - __half2float(h1));
    *(__half2*)(ol + o) = lv;
  }
}

// --------- elementwise f32 -> fp16 convert (+ optional count zeroing) ---------
__global__ void convert_h(const float* __restrict__ in, __half* __restrict__ out, int n,
                          int* __restrict__ count) {
  if (count && blockIdx.x == 0 && threadIdx.x < NE) count[threadIdx.x] = 0;
  int i = (blockIdx.x * 256 + threadIdx.x) * 8;
  if (i >= n) return;
  float4 a = *(const float4*)(in + i);
  float4 b = *(const float4*)(in + i + 4);
  uint4 o;
  o.x = packh2(a.x, a.y);
  o.y = packh2(a.z, a.w);
  o.z = packh2(b.x, b.y);
  o.w = packh2(b.z, b.w);
  *(uint4*)(out + i) = o;
}

// ---------------- LayerNorm (LN1: fp16 hi/lo) ----------------
__global__ void ln_kernel(const float* __restrict__ in, const float* __restrict__ gam,
                          const float* __restrict__ bet,
                          __half* __restrict__ oh, __half* __restrict__ ol) {
  __shared__ float red[256];
  int row = blockIdx.x, tid = threadIdx.x;
  const float* x = in + (size_t)row * DIM;
  float v0 = x[tid], v1 = x[tid+256], v2 = x[tid+512];
  red[tid] = v0+v1+v2; __syncthreads();
  for (int o=128;o;o>>=1){ if (tid<o) red[tid]+=red[tid+o]; __syncthreads(); }
  float mean = red[0] * (1.0f/DIM);
  __syncthreads();
  float d0=v0-mean, d1=v1-mean, d2=v2-mean;
  red[tid] = d0*d0+d1*d1+d2*d2; __syncthreads();
  for (int o=128;o;o>>=1){ if (tid<o) red[tid]+=red[tid+o]; __syncthreads(); }
  float r = rsqrtf(red[0]*(1.0f/DIM) + 1e-5f);
  size_t base = (size_t)row * DIM;
  #pragma unroll
  for (int j = 0; j < 3; j++) {
    int c = tid + j*256;
    float d = (j==0) ? d0 : (j==1) ? d1 : d2;
    float v = d*r*gam[c] + bet[c];
    __half h = __float2half_rn(v);
    oh[base + c] = h;
    ol[base + c] = __float2half_rn(v - __half2float(h));
  }
}

// ---------- Fused LN2 + router: LN -> fp16, x1 -> out copy, logits -> top2 ----------
__global__ void ln2_router(const float* __restrict__ in, const float* __restrict__ gam,
                           const float* __restrict__ bet, const float* __restrict__ Wr,
                           __half* __restrict__ oh, float* __restrict__ ocopy,
                           int* __restrict__ bucket, float* __restrict__ pairw,
                           int* __restrict__ count) {
  __shared__ float red[256];
  __shared__ float part[8][NE];
  int row = blockIdx.x, tid = threadIdx.x;
  int wid = tid >> 5, lane = tid & 31;
  const float* x = in + (size_t)row * DIM;
  float v0 = x[tid], v1 = x[tid+256], v2 = x[tid+512];
  red[tid] = v0+v1+v2; __syncthreads();
  for (int o=128;o;o>>=1){ if (tid<o) red[tid]+=red[tid+o]; __syncthreads(); }
  float mean = red[0] * (1.0f/DIM);
  __syncthreads();
  float d0=v0-mean, d1=v1-mean, d2=v2-mean;
  red[tid] = d0*d0+d1*d1+d2*d2; __syncthreads();
  for (int o=128;o;o>>=1){ if (tid<o) red[tid]+=red[tid+o]; __syncthreads(); }
  float r = rsqrtf(red[0]*(1.0f/DIM) + 1e-5f);
  size_t base = (size_t)row * DIM;
  float ln[3];
  #pragma unroll
  for (int j = 0; j < 3; j++) {
    int c = tid + j*256;
    float raw = (j==0) ? v0 : (j==1) ? v1 : v2;
    float d = (j==0) ? d0 : (j==1) ? d1 : d2;
    float v = d*r*gam[c] + bet[c];
    ln[j] = v;
    ocopy[base + c] = raw;
    oh[base + c] = __float2half_rn(v);
  }
  // router logits
  float lg[NE];
  #pragma unroll
  for (int e = 0; e < NE; e++) {
    lg[e] = ln[0]*Wr[tid*NE + e] + ln[1]*Wr[(tid+256)*NE + e] + ln[2]*Wr[(tid+512)*NE + e];
    #pragma unroll
    for (int off = 16; off; off >>= 1) lg[e] += __shfl_xor_sync(0xffffffffu, lg[e], off);
  }
  if (lane == 0) {
    #pragma unroll
    for (int e = 0; e < NE; e++) part[wid][e] = lg[e];
  }
  __syncthreads();
  if (tid == 0) {
    float L[NE];
    #pragma unroll
    for (int e = 0; e < NE; e++) {
      float s = 0.f;
      #pragma unroll
      for (int w = 0; w < 8; w++) s += part[w][e];
      L[e] = s;
    }
    int i0 = 0;
    #pragma unroll
    for (int e = 1; e < NE; e++) if (L[e] > L[i0]) i0 = e;
    int i1 = (i0 == 0) ? 1 : 0;
    #pragma unroll
    for (int e = 0; e < NE; e++) { if (e == i0) continue; if (L[e] > L[i1]) i1 = e; }
    float w0 = 1.f / (1.f + expf(L[i1] - L[i0]));
    float w1 = 1.f - w0;
    int p0 = row*2, p1 = row*2 + 1;
    pairw[p0] = w0; pairw[p1] = w1;
    int q0 = atomicAdd(&count[i0], 1); bucket[i0*NPAIR + q0] = p0;
    int q1 = atomicAdd(&count[i1], 1); bucket[i1*NPAIR + q1] = p1;
  }
}

extern "C" void kernel_launch(void* const* d_in, const int* in_sizes, int n_in,
                              void* d_out, int out_size) {
  const float* x       = (const float*)d_in[0];
  const float* Wqkv    = (const float*)d_in[1];
  const float* Wproj   = (const float*)d_in[2];
  const float* Wrouter = (const float*)d_in[3];
  const float* W1      = (const float*)d_in[4];
  const float* W2      = (const float*)d_in[5];
  const float* ln1g    = (const float*)d_in[6];
  const float* ln1b    = (const float*)d_in[7];
  const float* ln2g    = (const float*)d_in[8];
  const float* ln2b    = (const float*)d_in[9];
  float* out = (float*)d_out;

  Scratch* s = nullptr;
  cudaGetSymbolAddress((void**)&s, g_s);

  cudaFuncSetAttribute(attn_tc, cudaFuncAttributeMaxDynamicSharedMemorySize, AT_SMEM);
  cudaFuncSetAttribute(gemm_split<0>, cudaFuncAttributeMaxDynamicSharedMemorySize, GSMEM_SPLIT);
  cudaFuncSetAttribute(gemm_split<1>, cudaFuncAttributeMaxDynamicSharedMemorySize, GSMEM_SPLIT);
  cudaFuncSetAttribute(gemm_moe<2>, cudaFuncAttributeMaxDynamicSharedMemorySize, GSMEM_MOE);
  cudaFuncSetAttribute(gemm_moe<3>, cudaFuncAttributeMaxDynamicSharedMemorySize, GSMEM_MOE);

  dim3 tb(32, 8);
  transpose_split<<<dim3(QKVN/32, DIM/32, 1), tb>>>(Wqkv, s->Wqkvth, s->Wqkvtl, DIM, QKVN);
  transpose_split<<<dim3(DIM/32, DIM/32, 1), tb>>>(Wproj, s->Wprojth, s->Wprojtl, DIM, DIM);
  convert_h<<<(NE*DIM*FFD)/2048, 256>>>(W1, s->W1h, NE*DIM*FFD, s->count);
  convert_h<<<(NE*FFD*DIM)/2048, 256>>>(W2, s->W2h, NE*FFD*DIM, nullptr);

  // x -> ln1 -> qkv(fp16 hi/lo, Q scaled) -> attention(TC) -> proj+residual -> x1
  ln_kernel<<<NTOK, 256>>>(x, ln1g, ln1b, s->xln1h, s->xln1l);
  gemm_split<0><<<dim3(QKVN/128, NTOK/128, 1), 256, GSMEM_SPLIT>>>(
      s->xln1h, s->xln1l, s->Wqkvth, s->Wqkvtl, nullptr, s->qkvh, s->qkvl,
      NTOK, QKVN, DIM, nullptr);
  attn_tc<<<dim3(TSEQ/128, NH, NB), 256, AT_SMEM>>>(s->qkvh, s->qkvl, s->attnh, s->attnl);
  gemm_split<1><<<dim3(DIM/128, NTOK/128, 1), 256, GSMEM_SPLIT>>>(
      s->attnh, s->attnl, s->Wprojth, s->Wprojtl, s->x1, nullptr, nullptr,
      NTOK, DIM, DIM, x);

  // x1 -> fused LN2+router (copies x1 into out) -> MoE (down accumulates into out)
  ln2_router<<<NTOK, 256>>>(s->x1, ln2g, ln2b, Wrouter, s->xln2h, out,
                            s->bucket, s->pairw, s->count);
  gemm_moe<2><<<dim3(FFD/128, NPAIR/128, NE), 256, GSMEM_MOE>>>(
      s->xln2h, s->W1h, nullptr, s->Hh, FFD, DIM, s->bucket, s->count, nullptr);
  gemm_moe<3><<<dim3(DIM/128, NPAIR/128, NE), 256, GSMEM_MOE>>>(
      s->Hh, s->W2h, out, nullptr, DIM, FFD, s->bucket, s->count, s->pairw);
}